// round 5
// baseline (speedup 1.0000x reference)
#include <cuda_runtime.h>
#include <math.h>

#define BATCH 8
#define CIN   64
#define COUT  128
#define EDIM  128
#define HIN   192
#define WIN   384
#define OH    96
#define OW    192
#define TOPK  32
#define OUT6_SIZE (BATCH*COUT*OH*OW)

// padded conv1->conv2 buffer: out row h at pr=h+1 (98 rows), out col w at pc=w+3 (200 cols)
#define P2H 98
#define P2W 200

typedef unsigned long long u64;

// ---- scratch (zero-initialized at module load; halo never written) ----
__device__ float d_out2p[BATCH*TOPK*P2H*P2W];
__device__ int   d_idx1[BATCH*TOPK];
__device__ float d_gv1 [BATCH*TOPK];
__device__ int   d_idx2[BATCH*TOPK];
__device__ float d_gv2 [BATCH*TOPK];
__device__ int   d_slot2[BATCH*COUT];

__device__ __forceinline__ float leaky(float v) { return v >= 0.f ? v : 0.2f * v; }

__device__ __forceinline__ u64 pk2(float lo, float hi) {
    u64 r; asm("mov.b64 %0, {%1, %2};" : "=l"(r) : "f"(lo), "f"(hi)); return r;
}
__device__ __forceinline__ void upk2(u64 v, float& lo, float& hi) {
    asm("mov.b64 {%0, %1}, %2;" : "=f"(lo), "=f"(hi) : "l"(v));
}
__device__ __forceinline__ void fma2(u64& d, u64 a, u64 b) {
    asm("fma.rn.f32x2 %0, %1, %2, %0;" : "+l"(d) : "l"(a), "l"(b));
}
__device__ __forceinline__ unsigned smem_u32(const void* p) {
    return (unsigned)__cvta_generic_to_shared(p);
}
__device__ __forceinline__ void cp4(unsigned dst, const void* src, int sz) {
    asm volatile("cp.async.ca.shared.global [%0], [%1], 4, %2;" :: "r"(dst), "l"(src), "r"(sz));
}
__device__ __forceinline__ void cp8(unsigned dst, const void* src) {
    asm volatile("cp.async.ca.shared.global [%0], [%1], 8;" :: "r"(dst), "l"(src));
}
__device__ __forceinline__ void cp16(unsigned dst, const void* src) {
    asm volatile("cp.async.ca.shared.global [%0], [%1], 16;" :: "r"(dst), "l"(src));
}
#define CP_COMMIT() asm volatile("cp.async.commit_group;")
#define CP_WAIT1()  asm volatile("cp.async.wait_group 1;")
#define CP_WAIT0()  asm volatile("cp.async.wait_group 0;")

// ============================================================================
// Gate: logits = emb @ W + b ; top-32 (tie-break lower idx) ; softmax ; scatter
// ============================================================================
__global__ void gate_kernel(const float* __restrict__ emb,
                            const float* __restrict__ g1w, const float* __restrict__ g1b,
                            const float* __restrict__ g2w, const float* __restrict__ g2b,
                            float* __restrict__ out) {
    const int b    = blockIdx.x;
    const int gate = blockIdx.y;
    const int c    = threadIdx.x;
    const float* gw = (gate == 0) ? g1w : g2w;
    const float* gb = (gate == 0) ? g1b : g2b;

    __shared__ float s_emb[EDIM];
    __shared__ float s_log[COUT];
    __shared__ float s_exp[COUT];

    s_emb[c] = emb[b * EDIM + c];
    __syncthreads();

    float l = gb[c];
    #pragma unroll 8
    for (int e = 0; e < EDIM; e++) l += s_emb[e] * gw[e * COUT + c];
    s_log[c] = l;
    __syncthreads();

    int rank = 0;
    float m = -1e30f;
    for (int j = 0; j < COUT; j++) {
        float lj = s_log[j];
        if (lj > l || (lj == l && j < c)) rank++;
        if (lj > m) m = lj;
    }
    bool sel = (rank < TOPK);
    float ev = sel ? expf(l - m) : 0.0f;
    s_exp[c] = ev;
    __syncthreads();

    float s = 0.f;
    for (int j = 0; j < COUT; j++) s += s_exp[j];
    float gv = ev / s;

    out[OUT6_SIZE + gate * (BATCH * COUT) + b * COUT + c] = gv;

    if (gate == 0) {
        if (sel) { d_idx1[b * TOPK + rank] = c; d_gv1[b * TOPK + rank] = gv; }
    } else {
        d_slot2[b * COUT + c] = sel ? rank : -1;
        if (sel) { d_idx2[b * TOPK + rank] = c; d_gv2[b * TOPK + rank] = gv; }
    }
}

// ============================================================================
// ds: dense 1x1 s2 conv + BN(eval). Gate2-selected channels: RAW ident
// (conv2 fuses add+leaky); else leaky(ident). grid (36,4,BATCH), block 256.
// ============================================================================
__global__ void __launch_bounds__(256, 2) ds_kernel(const float* __restrict__ x,
                                                    const float* __restrict__ dsw,
                                                    const float* __restrict__ gamma,
                                                    const float* __restrict__ beta,
                                                    float* __restrict__ out) {
    const int b    = blockIdx.z;
    const int cgy  = blockIdx.y;
    const int tile = blockIdx.x;
    const int h0 = (tile / 3) * 8;
    const int w0 = (tile % 3) * 64;
    const int tid = threadIdx.x;
    const int cog = tid >> 7;
    const int t   = tid & 127;
    const int row = t >> 4;
    const int cq  = t & 15;
    const int h = h0 + row, w = w0 + 4 * cq;

    __shared__ __align__(16) float s_w[CIN][64];
    __shared__ float s_scale[32];
    __shared__ float s_beta[32];
    __shared__ int   s_slot[32];

    for (int i = tid; i < CIN * 32; i += 256) {
        int ci = i >> 5, co = i & 31;
        float wv = dsw[(cgy * 32 + co) * CIN + ci];
        s_w[ci][2 * co] = wv; s_w[ci][2 * co + 1] = wv;
    }
    if (tid < 32) {
        int c = cgy * 32 + tid;
        s_scale[tid] = gamma[c] * rsqrtf(1.0f + 1e-5f);
        s_beta[tid]  = beta[c];
        s_slot[tid]  = d_slot2[b * COUT + c];
    }
    __syncthreads();

    u64 acc[16][2];
    #pragma unroll
    for (int i = 0; i < 16; i++) { acc[i][0] = 0ull; acc[i][1] = 0ull; }

    const float* xb = x + ((size_t)b * CIN * HIN + 2 * h) * WIN + 2 * w;
    #pragma unroll 4
    for (int ci = 0; ci < CIN; ci++) {
        const float* p = xb + (size_t)ci * HIN * WIN;
        float4 A = *(const float4*)(p);
        float4 B = *(const float4*)(p + 4);
        u64 xa = pk2(A.x, A.z);
        u64 xc = pk2(B.x, B.z);
        const u64* wr = (const u64*)&s_w[ci][cog * 32];
        #pragma unroll
        for (int j = 0; j < 8; j++) {
            ulonglong2 q = *(const ulonglong2*)(wr + 2 * j);
            fma2(acc[2*j][0],   xa, q.x); fma2(acc[2*j][1],   xc, q.x);
            fma2(acc[2*j+1][0], xa, q.y); fma2(acc[2*j+1][1], xc, q.y);
        }
    }

    #pragma unroll
    for (int j = 0; j < 16; j++) {
        int co = cog * 16 + j;
        int c = cgy * 32 + co;
        float v0, v1, v2, v3;
        upk2(acc[j][0], v0, v1);
        upk2(acc[j][1], v2, v3);
        float sc = s_scale[co], be = s_beta[co];
        v0 = v0 * sc + be; v1 = v1 * sc + be; v2 = v2 * sc + be; v3 = v3 * sc + be;
        float4 o;
        if (s_slot[co] < 0) {
            o.x = leaky(v0); o.y = leaky(v1); o.z = leaky(v2); o.w = leaky(v3);
        } else {
            o.x = v0; o.y = v1; o.z = v2; o.w = v3;   // raw; conv2 finishes it
        }
        *(float4*)&out[((size_t)(b * COUT + c) * OH + h) * OW + w] = o;
    }
}

// ============================================================================
// conv1: 3x3 s2 p1, 32 gated channels. Thread: 8 co x 8 px.
// Block 256 = 4 cog x (8 rows x 8 col-octets). grid (36, BATCH).
// s_x: cl <-> input col 2w0-1+cl, rows 0..16 <-> input 2h0-1+r.
// s_w: [2 buf][4 planes][32 co][24] (kernel row r at 8r..8r+5, dup pairs).
// ============================================================================
#define C1_XSTR 132
__global__ void __launch_bounds__(256, 2) conv1_kernel(const float* __restrict__ x,
                                                       const float* __restrict__ w1) {
    const int b = blockIdx.y, tile = blockIdx.x;
    const int h0 = (tile / 3) * 8, w0 = (tile % 3) * 64;
    const int tid = threadIdx.x;
    const int cog = tid >> 6;
    const int t   = tid & 63;
    const int row = t >> 3;
    const int c8  = t & 7;

    __shared__ int   s_idx[TOPK];
    __shared__ float s_gv[TOPK];
    __shared__ __align__(16) float s_w[2][4 * TOPK * 24];   // 24.6 KB
    __shared__ __align__(16) float s_x[2][17 * C1_XSTR];    // 17.9 KB

    if (tid < TOPK) { s_idx[tid] = d_idx1[b * TOPK + tid]; s_gv[tid] = d_gv1[b * TOPK + tid]; }
    __syncthreads();

    u64 acc[8][4];
    #pragma unroll
    for (int i = 0; i < 8; i++)
        #pragma unroll
        for (int m = 0; m < 4; m++) acc[i][m] = 0ull;

    // prologue: weights chunk0 + x plane0
    {
        for (int i = tid; i < 4 * TOPK * 9; i += 256) {
            int ci_l = i / (TOPK * 9);
            int r = i - ci_l * (TOPK * 9);
            int co = r / 9, k = r - co * 9;
            const float* src = w1 + (s_idx[co] * CIN + ci_l) * 9 + k;
            unsigned dst = smem_u32(&s_w[0][(ci_l * TOPK + co) * 24 + (k / 3) * 8 + (k % 3) * 2]);
            cp4(dst, src, 4); cp4(dst + 4, src, 4);
        }
        const float* sp = x + (size_t)(b * CIN + 0) * HIN * WIN;
        for (int i = tid; i < 17 * 129; i += 256) {
            int r = i / 129, cl = i - r * 129;
            int gr = 2 * h0 - 1 + r, gc = 2 * w0 - 1 + cl;
            int ok = (gr >= 0 && gr < HIN && gc >= 0 && gc < WIN) ? 4 : 0;
            cp4(smem_u32(&s_x[0][r * C1_XSTR + cl]), sp + gr * WIN + gc, ok);
        }
        CP_COMMIT();
    }

    for (int s = 0; s < CIN; s++) {
        if (s + 1 < CIN) {
            const int sn = s + 1;
            if ((sn & 3) == 0) {
                const int chunk = sn >> 2, wb = chunk & 1;
                for (int i = tid; i < 4 * TOPK * 9; i += 256) {
                    int ci_l = i / (TOPK * 9);
                    int r = i - ci_l * (TOPK * 9);
                    int co = r / 9, k = r - co * 9;
                    const float* src = w1 + (s_idx[co] * CIN + chunk * 4 + ci_l) * 9 + k;
                    unsigned dst = smem_u32(&s_w[wb][(ci_l * TOPK + co) * 24 + (k / 3) * 8 + (k % 3) * 2]);
                    cp4(dst, src, 4); cp4(dst + 4, src, 4);
                }
            }
            const float* sp = x + (size_t)(b * CIN + sn) * HIN * WIN;
            const int xb2 = sn & 1;
            for (int i = tid; i < 17 * 129; i += 256) {
                int r = i / 129, cl = i - r * 129;
                int gr = 2 * h0 - 1 + r, gc = 2 * w0 - 1 + cl;
                int ok = (gr >= 0 && gr < HIN && gc >= 0 && gc < WIN) ? 4 : 0;
                cp4(smem_u32(&s_x[xb2][r * C1_XSTR + cl]), sp + gr * WIN + gc, ok);
            }
            CP_COMMIT();
            CP_WAIT1();
        } else {
            CP_WAIT0();
        }
        __syncthreads();

        {
            const float* xp = &s_x[s & 1][(2 * row) * C1_XSTR + 16 * c8];
            const float* wcb = &s_w[(s >> 2) & 1][((s & 3) * TOPK + cog * 8) * 24];
            #pragma unroll
            for (int r = 0; r < 3; r++) {
                const float* rp = xp + r * C1_XSTR;
                float4 A0 = *(const float4*)(rp);
                float4 A1 = *(const float4*)(rp + 4);
                float4 A2 = *(const float4*)(rp + 8);
                float4 A3 = *(const float4*)(rp + 12);
                float2 E  = *(const float2*)(rp + 16);
                u64 S[4][3];
                S[0][0] = pk2(A0.x, A0.z); S[0][1] = pk2(A0.y, A0.w); S[0][2] = pk2(A0.z, A1.x);
                S[1][0] = pk2(A1.x, A1.z); S[1][1] = pk2(A1.y, A1.w); S[1][2] = pk2(A1.z, A2.x);
                S[2][0] = pk2(A2.x, A2.z); S[2][1] = pk2(A2.y, A2.w); S[2][2] = pk2(A2.z, A3.x);
                S[3][0] = pk2(A3.x, A3.z); S[3][1] = pk2(A3.y, A3.w); S[3][2] = pk2(A3.z, E.x);
                #pragma unroll
                for (int j = 0; j < 8; j++) {
                    const u64* wp = (const u64*)(wcb + j * 24 + r * 8);
                    ulonglong2 qq = *(const ulonglong2*)wp;
                    u64 q2 = wp[2];
                    #pragma unroll
                    for (int m = 0; m < 4; m++) {
                        fma2(acc[j][m], S[m][0], qq.x);
                        fma2(acc[j][m], S[m][1], qq.y);
                        fma2(acc[j][m], S[m][2], q2);
                    }
                }
            }
        }
        __syncthreads();
    }

    const int h = h0 + row, w = w0 + 8 * c8;
    #pragma unroll
    for (int j = 0; j < 8; j++) {
        int co = cog * 8 + j;
        float g = s_gv[co];
        float* base = &d_out2p[((size_t)(b * TOPK + co) * P2H + h + 1) * P2W + (w + 3)];
        #pragma unroll
        for (int m = 0; m < 4; m++) {
            float lo, hi; upk2(acc[j][m], lo, hi);
            base[2 * m]     = leaky(lo * g);
            base[2 * m + 1] = leaky(hi * g);
        }
    }
}

// ============================================================================
// conv2: 3x3 s1 p1, 32 compact in -> 32 gated out; fused epilogue:
// out = leaky(leaky(conv*g2) + ident_raw). Thread: 8 co x 8 px. grid (36, BATCH).
// s_x: cl = (input col - (w0-1)) + 2, cl in 2..67, stride 72.
// ============================================================================
#define C2_XSTR 72
__global__ void __launch_bounds__(256, 2) conv2_kernel(const float* __restrict__ w2,
                                                       float* __restrict__ out) {
    const int b = blockIdx.y, tile = blockIdx.x;
    const int h0 = (tile / 3) * 8, w0 = (tile % 3) * 64;
    const int tid = threadIdx.x;
    const int cog = tid >> 6;
    const int t   = tid & 63;
    const int row = t >> 3;
    const int c8  = t & 7;

    __shared__ int   s_idx1[TOPK];
    __shared__ int   s_idx2[TOPK];
    __shared__ float s_gv[TOPK];
    __shared__ __align__(16) float s_w[2][4 * TOPK * 24];   // 24.6 KB
    __shared__ __align__(16) float s_x[2][10 * C2_XSTR];    // 5.8 KB

    if (tid < TOPK) {
        s_idx1[tid] = d_idx1[b * TOPK + tid];
        s_idx2[tid] = d_idx2[b * TOPK + tid];
        s_gv[tid]   = d_gv2[b * TOPK + tid];
    }
    __syncthreads();

    u64 acc[8][4];
    #pragma unroll
    for (int i = 0; i < 8; i++)
        #pragma unroll
        for (int m = 0; m < 4; m++) acc[i][m] = 0ull;

    // staging: per row: cp8 (cl 2..3 <- pc w0+2) + 16x cp16 (cl 4+4t <- pc w0+4+4t)
    // prologue
    {
        for (int i = tid; i < 4 * TOPK * 9; i += 256) {
            int ci_l = i / (TOPK * 9);
            int r = i - ci_l * (TOPK * 9);
            int co = r / 9, k = r - co * 9;
            const float* src = w2 + (s_idx2[co] * COUT + s_idx1[ci_l]) * 9 + k;
            unsigned dst = smem_u32(&s_w[0][(ci_l * TOPK + co) * 24 + (k / 3) * 8 + (k % 3) * 2]);
            cp4(dst, src, 4); cp4(dst + 4, src, 4);
        }
        const float* sp = d_out2p + (size_t)(b * TOPK + 0) * P2H * P2W;
        for (int i = tid; i < 10 * 17; i += 256) {
            int r = i / 17, u = i - r * 17;
            const float* srow = sp + (size_t)(h0 + r) * P2W + w0;
            if (u == 0) cp8(smem_u32(&s_x[0][r * C2_XSTR + 2]), srow + 2);
            else        cp16(smem_u32(&s_x[0][r * C2_XSTR + 4 * u]), srow + 4 * u);
        }
        CP_COMMIT();
    }

    for (int s = 0; s < TOPK; s++) {
        if (s + 1 < TOPK) {
            const int sn = s + 1;
            if ((sn & 3) == 0) {
                const int chunk = sn >> 2, wb = chunk & 1;
                for (int i = tid; i < 4 * TOPK * 9; i += 256) {
                    int ci_l = i / (TOPK * 9);
                    int r = i - ci_l * (TOPK * 9);
                    int co = r / 9, k = r - co * 9;
                    const float* src = w2 + (s_idx2[co] * COUT + s_idx1[chunk * 4 + ci_l]) * 9 + k;
                    unsigned dst = smem_u32(&s_w[wb][(ci_l * TOPK + co) * 24 + (k / 3) * 8 + (k % 3) * 2]);
                    cp4(dst, src, 4); cp4(dst + 4, src, 4);
                }
            }
            const float* sp = d_out2p + (size_t)(b * TOPK + sn) * P2H * P2W;
            const int xb2 = sn & 1;
            for (int i = tid; i < 10 * 17; i += 256) {
                int r = i / 17, u = i - r * 17;
                const float* srow = sp + (size_t)(h0 + r) * P2W + w0;
                if (u == 0) cp8(smem_u32(&s_x[xb2][r * C2_XSTR + 2]), srow + 2);
                else        cp16(smem_u32(&s_x[xb2][r * C2_XSTR + 4 * u]), srow + 4 * u);
            }
            CP_COMMIT();
            CP_WAIT1();
        } else {
            CP_WAIT0();
        }
        __syncthreads();

        {
            // xin[d] at cl = 8*c8 + 2 + d, d = 0..9 (input cols wb-1 .. wb+8)
            const float* xp = &s_x[s & 1][row * C2_XSTR + 8 * c8 + 2];
            const float* wcb = &s_w[(s >> 2) & 1][((s & 3) * TOPK + cog * 8) * 24];
            #pragma unroll
            for (int r = 0; r < 3; r++) {
                const float* rp = xp + r * C2_XSTR;
                float2 F  = *(const float2*)(rp);       // xin[0,1]
                float4 A  = *(const float4*)(rp + 2);   // xin[2..5]
                float4 Bv = *(const float4*)(rp + 6);   // xin[6..9]
                u64 Q[9];
                Q[0] = pk2(F.x, F.y);  Q[1] = pk2(F.y, A.x);  Q[2] = pk2(A.x, A.y);
                Q[3] = pk2(A.y, A.z);  Q[4] = pk2(A.z, A.w);  Q[5] = pk2(A.w, Bv.x);
                Q[6] = pk2(Bv.x, Bv.y); Q[7] = pk2(Bv.y, Bv.z); Q[8] = pk2(Bv.z, Bv.w);
                #pragma unroll
                for (int j = 0; j < 8; j++) {
                    const u64* wp = (const u64*)(wcb + j * 24 + r * 8);
                    ulonglong2 qq = *(const ulonglong2*)wp;
                    u64 q2 = wp[2];
                    #pragma unroll
                    for (int m = 0; m < 4; m++) {
                        fma2(acc[j][m], Q[2 * m],     qq.x);
                        fma2(acc[j][m], Q[2 * m + 1], qq.y);
                        fma2(acc[j][m], Q[2 * m + 2], q2);
                    }
                }
            }
        }
        __syncthreads();
    }

    const int h = h0 + row, w = w0 + 8 * c8;
    #pragma unroll
    for (int j = 0; j < 8; j++) {
        int co = cog * 8 + j;
        float g = s_gv[co];
        int c = s_idx2[co];
        float* base = &out[((size_t)(b * COUT + c) * OH + h) * OW + w];
        float4 id0 = *(const float4*)base;
        float4 id1 = *(const float4*)(base + 4);
        float v[8];
        #pragma unroll
        for (int m = 0; m < 4; m++) upk2(acc[j][m], v[2 * m], v[2 * m + 1]);
        float4 o0, o1;
        o0.x = leaky(leaky(v[0] * g) + id0.x);
        o0.y = leaky(leaky(v[1] * g) + id0.y);
        o0.z = leaky(leaky(v[2] * g) + id0.z);
        o0.w = leaky(leaky(v[3] * g) + id0.w);
        o1.x = leaky(leaky(v[4] * g) + id1.x);
        o1.y = leaky(leaky(v[5] * g) + id1.y);
        o1.z = leaky(leaky(v[6] * g) + id1.z);
        o1.w = leaky(leaky(v[7] * g) + id1.w);
        *(float4*)base = o0;
        *(float4*)(base + 4) = o1;
    }
}

// ============================================================================
extern "C" void kernel_launch(void* const* d_in, const int* in_sizes, int n_in,
                              void* d_out, int out_size) {
    const float* x     = (const float*)d_in[0];
    const float* emb   = (const float*)d_in[1];
    const float* w1    = (const float*)d_in[2];
    const float* w2    = (const float*)d_in[3];
    const float* dsw   = (const float*)d_in[4];
    const float* gam   = (const float*)d_in[5];
    const float* bet   = (const float*)d_in[6];
    const float* g1w   = (const float*)d_in[7];
    const float* g1b   = (const float*)d_in[8];
    const float* g2w   = (const float*)d_in[9];
    const float* g2b   = (const float*)d_in[10];
    float* out = (float*)d_out;

    gate_kernel<<<dim3(BATCH, 2), 128>>>(emb, g1w, g1b, g2w, g2b, out);
    ds_kernel<<<dim3(36, 4, BATCH), 256>>>(x, dsw, gam, bet, out);
    conv1_kernel<<<dim3(36, BATCH), 256>>>(x, w1);
    conv2_kernel<<<dim3(36, BATCH), 256>>>(w2, out);
}

// round 6
// speedup vs baseline: 1.0006x; 1.0006x over previous
#include <cuda_runtime.h>
#include <math.h>

#define BATCH 8
#define CIN   64
#define COUT  128
#define EDIM  128
#define HIN   192
#define WIN   384
#define OH    96
#define OW    192
#define TOPK  32
#define OUT6_SIZE (BATCH*COUT*OH*OW)

// padded conv1->conv2 buffer: out row h at pr=h+1 (98 rows), out col w at pc=w+3 (200 cols)
#define P2H 98
#define P2W 200

typedef unsigned long long u64;

// ---- scratch (zero-initialized at module load; halo never written) ----
__device__ float d_out2p[BATCH*TOPK*P2H*P2W];
__device__ int   d_idx1[BATCH*TOPK];
__device__ float d_gv1 [BATCH*TOPK];
__device__ int   d_idx2[BATCH*TOPK];
__device__ float d_gv2 [BATCH*TOPK];
__device__ int   d_slot2[BATCH*COUT];

__device__ __forceinline__ float leaky(float v) { return v >= 0.f ? v : 0.2f * v; }

__device__ __forceinline__ u64 pk2(float lo, float hi) {
    u64 r; asm("mov.b64 %0, {%1, %2};" : "=l"(r) : "f"(lo), "f"(hi)); return r;
}
__device__ __forceinline__ void upk2(u64 v, float& lo, float& hi) {
    asm("mov.b64 {%0, %1}, %2;" : "=f"(lo), "=f"(hi) : "l"(v));
}
__device__ __forceinline__ void fma2(u64& d, u64 a, u64 b) {
    asm("fma.rn.f32x2 %0, %1, %2, %0;" : "+l"(d) : "l"(a), "l"(b));
}
__device__ __forceinline__ unsigned smem_u32(const void* p) {
    return (unsigned)__cvta_generic_to_shared(p);
}
__device__ __forceinline__ void cp4(unsigned dst, const void* src, int sz) {
    asm volatile("cp.async.ca.shared.global [%0], [%1], 4, %2;" :: "r"(dst), "l"(src), "r"(sz));
}
__device__ __forceinline__ void cp8(unsigned dst, const void* src) {
    asm volatile("cp.async.ca.shared.global [%0], [%1], 8;" :: "r"(dst), "l"(src));
}
__device__ __forceinline__ void cp16(unsigned dst, const void* src) {
    asm volatile("cp.async.ca.shared.global [%0], [%1], 16;" :: "r"(dst), "l"(src));
}
#define CP_COMMIT() asm volatile("cp.async.commit_group;")
#define CP_WAIT1()  asm volatile("cp.async.wait_group 1;")
#define CP_WAIT0()  asm volatile("cp.async.wait_group 0;")

// ============================================================================
// Gate: logits = emb @ W + b ; top-32 (tie-break lower idx) ; softmax ; scatter
// ============================================================================
__global__ void gate_kernel(const float* __restrict__ emb,
                            const float* __restrict__ g1w, const float* __restrict__ g1b,
                            const float* __restrict__ g2w, const float* __restrict__ g2b,
                            float* __restrict__ out) {
    const int b    = blockIdx.x;
    const int gate = blockIdx.y;
    const int c    = threadIdx.x;
    const float* gw = (gate == 0) ? g1w : g2w;
    const float* gb = (gate == 0) ? g1b : g2b;

    __shared__ float s_emb[EDIM];
    __shared__ float s_log[COUT];
    __shared__ float s_exp[COUT];

    s_emb[c] = emb[b * EDIM + c];
    __syncthreads();

    float l = gb[c];
    #pragma unroll 8
    for (int e = 0; e < EDIM; e++) l += s_emb[e] * gw[e * COUT + c];
    s_log[c] = l;
    __syncthreads();

    int rank = 0;
    float m = -1e30f;
    for (int j = 0; j < COUT; j++) {
        float lj = s_log[j];
        if (lj > l || (lj == l && j < c)) rank++;
        if (lj > m) m = lj;
    }
    bool sel = (rank < TOPK);
    float ev = sel ? expf(l - m) : 0.0f;
    s_exp[c] = ev;
    __syncthreads();

    float s = 0.f;
    for (int j = 0; j < COUT; j++) s += s_exp[j];
    float gv = ev / s;

    out[OUT6_SIZE + gate * (BATCH * COUT) + b * COUT + c] = gv;

    if (gate == 0) {
        if (sel) { d_idx1[b * TOPK + rank] = c; d_gv1[b * TOPK + rank] = gv; }
    } else {
        d_slot2[b * COUT + c] = sel ? rank : -1;
        if (sel) { d_idx2[b * TOPK + rank] = c; d_gv2[b * TOPK + rank] = gv; }
    }
}

// ============================================================================
// ds: dense 1x1 s2 conv + BN(eval). Gate2-selected channels: RAW ident
// (conv2 fuses add+leaky); else leaky(ident). grid (36,4,BATCH), block 256.
// ============================================================================
__global__ void __launch_bounds__(256, 2) ds_kernel(const float* __restrict__ x,
                                                    const float* __restrict__ dsw,
                                                    const float* __restrict__ gamma,
                                                    const float* __restrict__ beta,
                                                    float* __restrict__ out) {
    const int b    = blockIdx.z;
    const int cgy  = blockIdx.y;
    const int tile = blockIdx.x;
    const int h0 = (tile / 3) * 8;
    const int w0 = (tile % 3) * 64;
    const int tid = threadIdx.x;
    const int cog = tid >> 7;
    const int t   = tid & 127;
    const int row = t >> 4;
    const int cq  = t & 15;
    const int h = h0 + row, w = w0 + 4 * cq;

    __shared__ __align__(16) float s_w[CIN][64];
    __shared__ float s_scale[32];
    __shared__ float s_beta[32];
    __shared__ int   s_slot[32];

    for (int i = tid; i < CIN * 32; i += 256) {
        int ci = i >> 5, co = i & 31;
        float wv = dsw[(cgy * 32 + co) * CIN + ci];
        s_w[ci][2 * co] = wv; s_w[ci][2 * co + 1] = wv;
    }
    if (tid < 32) {
        int c = cgy * 32 + tid;
        s_scale[tid] = gamma[c] * rsqrtf(1.0f + 1e-5f);
        s_beta[tid]  = beta[c];
        s_slot[tid]  = d_slot2[b * COUT + c];
    }
    __syncthreads();

    u64 acc[16][2];
    #pragma unroll
    for (int i = 0; i < 16; i++) { acc[i][0] = 0ull; acc[i][1] = 0ull; }

    const float* xb = x + ((size_t)b * CIN * HIN + 2 * h) * WIN + 2 * w;
    #pragma unroll 4
    for (int ci = 0; ci < CIN; ci++) {
        const float* p = xb + (size_t)ci * HIN * WIN;
        float4 A = *(const float4*)(p);
        float4 B = *(const float4*)(p + 4);
        u64 xa = pk2(A.x, A.z);
        u64 xc = pk2(B.x, B.z);
        const u64* wr = (const u64*)&s_w[ci][cog * 32];
        #pragma unroll
        for (int j = 0; j < 8; j++) {
            ulonglong2 q = *(const ulonglong2*)(wr + 2 * j);
            fma2(acc[2*j][0],   xa, q.x); fma2(acc[2*j][1],   xc, q.x);
            fma2(acc[2*j+1][0], xa, q.y); fma2(acc[2*j+1][1], xc, q.y);
        }
    }

    #pragma unroll
    for (int j = 0; j < 16; j++) {
        int co = cog * 16 + j;
        int c = cgy * 32 + co;
        float v0, v1, v2, v3;
        upk2(acc[j][0], v0, v1);
        upk2(acc[j][1], v2, v3);
        float sc = s_scale[co], be = s_beta[co];
        v0 = v0 * sc + be; v1 = v1 * sc + be; v2 = v2 * sc + be; v3 = v3 * sc + be;
        float4 o;
        if (s_slot[co] < 0) {
            o.x = leaky(v0); o.y = leaky(v1); o.z = leaky(v2); o.w = leaky(v3);
        } else {
            o.x = v0; o.y = v1; o.z = v2; o.w = v3;   // raw; conv2 finishes it
        }
        *(float4*)&out[((size_t)(b * COUT + c) * OH + h) * OW + w] = o;
    }
}

// ============================================================================
// conv1: 3x3 s2 p1, 32 gated channels. Thread: 8 co x 8 px.
// Block 256 = 4 cog x (8 rows x 8 col-octets). grid (36, BATCH).
// s_x: cl <-> input col 2w0-1+cl, rows 0..16 <-> input 2h0-1+r.
// s_w: [2 buf][4 planes][32 co][24] (kernel row r at 8r..8r+5, dup pairs).
// ============================================================================
#define C1_XSTR 132
__global__ void __launch_bounds__(256, 2) conv1_kernel(const float* __restrict__ x,
                                                       const float* __restrict__ w1) {
    const int b = blockIdx.y, tile = blockIdx.x;
    const int h0 = (tile / 3) * 8, w0 = (tile % 3) * 64;
    const int tid = threadIdx.x;
    const int cog = tid >> 6;
    const int t   = tid & 63;
    const int row = t >> 3;
    const int c8  = t & 7;

    __shared__ int   s_idx[TOPK];
    __shared__ float s_gv[TOPK];
    __shared__ __align__(16) float s_w[2][4 * TOPK * 24];   // 24.6 KB
    __shared__ __align__(16) float s_x[2][17 * C1_XSTR];    // 17.9 KB

    if (tid < TOPK) { s_idx[tid] = d_idx1[b * TOPK + tid]; s_gv[tid] = d_gv1[b * TOPK + tid]; }
    __syncthreads();

    u64 acc[8][4];
    #pragma unroll
    for (int i = 0; i < 8; i++)
        #pragma unroll
        for (int m = 0; m < 4; m++) acc[i][m] = 0ull;

    // prologue: weights chunk0 + x plane0
    {
        for (int i = tid; i < 4 * TOPK * 9; i += 256) {
            int ci_l = i / (TOPK * 9);
            int r = i - ci_l * (TOPK * 9);
            int co = r / 9, k = r - co * 9;
            const float* src = w1 + (s_idx[co] * CIN + ci_l) * 9 + k;
            unsigned dst = smem_u32(&s_w[0][(ci_l * TOPK + co) * 24 + (k / 3) * 8 + (k % 3) * 2]);
            cp4(dst, src, 4); cp4(dst + 4, src, 4);
        }
        const float* sp = x + (size_t)(b * CIN + 0) * HIN * WIN;
        for (int i = tid; i < 17 * 129; i += 256) {
            int r = i / 129, cl = i - r * 129;
            int gr = 2 * h0 - 1 + r, gc = 2 * w0 - 1 + cl;
            int ok = (gr >= 0 && gr < HIN && gc >= 0 && gc < WIN) ? 4 : 0;
            cp4(smem_u32(&s_x[0][r * C1_XSTR + cl]), sp + gr * WIN + gc, ok);
        }
        CP_COMMIT();
    }

    for (int s = 0; s < CIN; s++) {
        if (s + 1 < CIN) {
            const int sn = s + 1;
            if ((sn & 3) == 0) {
                const int chunk = sn >> 2, wb = chunk & 1;
                for (int i = tid; i < 4 * TOPK * 9; i += 256) {
                    int ci_l = i / (TOPK * 9);
                    int r = i - ci_l * (TOPK * 9);
                    int co = r / 9, k = r - co * 9;
                    const float* src = w1 + (s_idx[co] * CIN + chunk * 4 + ci_l) * 9 + k;
                    unsigned dst = smem_u32(&s_w[wb][(ci_l * TOPK + co) * 24 + (k / 3) * 8 + (k % 3) * 2]);
                    cp4(dst, src, 4); cp4(dst + 4, src, 4);
                }
            }
            const float* sp = x + (size_t)(b * CIN + sn) * HIN * WIN;
            const int xb2 = sn & 1;
            for (int i = tid; i < 17 * 129; i += 256) {
                int r = i / 129, cl = i - r * 129;
                int gr = 2 * h0 - 1 + r, gc = 2 * w0 - 1 + cl;
                int ok = (gr >= 0 && gr < HIN && gc >= 0 && gc < WIN) ? 4 : 0;
                cp4(smem_u32(&s_x[xb2][r * C1_XSTR + cl]), sp + gr * WIN + gc, ok);
            }
            CP_COMMIT();
            CP_WAIT1();
        } else {
            CP_WAIT0();
        }
        __syncthreads();

        {
            const float* xp = &s_x[s & 1][(2 * row) * C1_XSTR + 16 * c8];
            const float* wcb = &s_w[(s >> 2) & 1][((s & 3) * TOPK + cog * 8) * 24];
            #pragma unroll
            for (int r = 0; r < 3; r++) {
                const float* rp = xp + r * C1_XSTR;
                float4 A0 = *(const float4*)(rp);
                float4 A1 = *(const float4*)(rp + 4);
                float4 A2 = *(const float4*)(rp + 8);
                float4 A3 = *(const float4*)(rp + 12);
                float2 E  = *(const float2*)(rp + 16);
                u64 S[4][3];
                S[0][0] = pk2(A0.x, A0.z); S[0][1] = pk2(A0.y, A0.w); S[0][2] = pk2(A0.z, A1.x);
                S[1][0] = pk2(A1.x, A1.z); S[1][1] = pk2(A1.y, A1.w); S[1][2] = pk2(A1.z, A2.x);
                S[2][0] = pk2(A2.x, A2.z); S[2][1] = pk2(A2.y, A2.w); S[2][2] = pk2(A2.z, A3.x);
                S[3][0] = pk2(A3.x, A3.z); S[3][1] = pk2(A3.y, A3.w); S[3][2] = pk2(A3.z, E.x);
                #pragma unroll
                for (int j = 0; j < 8; j++) {
                    const u64* wp = (const u64*)(wcb + j * 24 + r * 8);
                    ulonglong2 qq = *(const ulonglong2*)wp;
                    u64 q2 = wp[2];
                    #pragma unroll
                    for (int m = 0; m < 4; m++) {
                        fma2(acc[j][m], S[m][0], qq.x);
                        fma2(acc[j][m], S[m][1], qq.y);
                        fma2(acc[j][m], S[m][2], q2);
                    }
                }
            }
        }
        __syncthreads();
    }

    const int h = h0 + row, w = w0 + 8 * c8;
    #pragma unroll
    for (int j = 0; j < 8; j++) {
        int co = cog * 8 + j;
        float g = s_gv[co];
        float* base = &d_out2p[((size_t)(b * TOPK + co) * P2H + h + 1) * P2W + (w + 3)];
        #pragma unroll
        for (int m = 0; m < 4; m++) {
            float lo, hi; upk2(acc[j][m], lo, hi);
            base[2 * m]     = leaky(lo * g);
            base[2 * m + 1] = leaky(hi * g);
        }
    }
}

// ============================================================================
// conv2: 3x3 s1 p1, 32 compact in -> 32 gated out; fused epilogue:
// out = leaky(leaky(conv*g2) + ident_raw). Thread: 8 co x 8 px. grid (36, BATCH).
// s_x: cl = (input col - (w0-1)) + 2, cl in 2..67, stride 72.
// ============================================================================
#define C2_XSTR 72
__global__ void __launch_bounds__(256, 2) conv2_kernel(const float* __restrict__ w2,
                                                       float* __restrict__ out) {
    const int b = blockIdx.y, tile = blockIdx.x;
    const int h0 = (tile / 3) * 8, w0 = (tile % 3) * 64;
    const int tid = threadIdx.x;
    const int cog = tid >> 6;
    const int t   = tid & 63;
    const int row = t >> 3;
    const int c8  = t & 7;

    __shared__ int   s_idx1[TOPK];
    __shared__ int   s_idx2[TOPK];
    __shared__ float s_gv[TOPK];
    __shared__ __align__(16) float s_w[2][4 * TOPK * 24];   // 24.6 KB
    __shared__ __align__(16) float s_x[2][10 * C2_XSTR];    // 5.8 KB

    if (tid < TOPK) {
        s_idx1[tid] = d_idx1[b * TOPK + tid];
        s_idx2[tid] = d_idx2[b * TOPK + tid];
        s_gv[tid]   = d_gv2[b * TOPK + tid];
    }
    __syncthreads();

    u64 acc[8][4];
    #pragma unroll
    for (int i = 0; i < 8; i++)
        #pragma unroll
        for (int m = 0; m < 4; m++) acc[i][m] = 0ull;

    // staging: per row: cp8 (cl 2..3 <- pc w0+2) + 16x cp16 (cl 4+4t <- pc w0+4+4t)
    // prologue
    {
        for (int i = tid; i < 4 * TOPK * 9; i += 256) {
            int ci_l = i / (TOPK * 9);
            int r = i - ci_l * (TOPK * 9);
            int co = r / 9, k = r - co * 9;
            const float* src = w2 + (s_idx2[co] * COUT + s_idx1[ci_l]) * 9 + k;
            unsigned dst = smem_u32(&s_w[0][(ci_l * TOPK + co) * 24 + (k / 3) * 8 + (k % 3) * 2]);
            cp4(dst, src, 4); cp4(dst + 4, src, 4);
        }
        const float* sp = d_out2p + (size_t)(b * TOPK + 0) * P2H * P2W;
        for (int i = tid; i < 10 * 17; i += 256) {
            int r = i / 17, u = i - r * 17;
            const float* srow = sp + (size_t)(h0 + r) * P2W + w0;
            if (u == 0) cp8(smem_u32(&s_x[0][r * C2_XSTR + 2]), srow + 2);
            else        cp16(smem_u32(&s_x[0][r * C2_XSTR + 4 * u]), srow + 4 * u);
        }
        CP_COMMIT();
    }

    for (int s = 0; s < TOPK; s++) {
        if (s + 1 < TOPK) {
            const int sn = s + 1;
            if ((sn & 3) == 0) {
                const int chunk = sn >> 2, wb = chunk & 1;
                for (int i = tid; i < 4 * TOPK * 9; i += 256) {
                    int ci_l = i / (TOPK * 9);
                    int r = i - ci_l * (TOPK * 9);
                    int co = r / 9, k = r - co * 9;
                    const float* src = w2 + (s_idx2[co] * COUT + s_idx1[chunk * 4 + ci_l]) * 9 + k;
                    unsigned dst = smem_u32(&s_w[wb][(ci_l * TOPK + co) * 24 + (k / 3) * 8 + (k % 3) * 2]);
                    cp4(dst, src, 4); cp4(dst + 4, src, 4);
                }
            }
            const float* sp = d_out2p + (size_t)(b * TOPK + sn) * P2H * P2W;
            const int xb2 = sn & 1;
            for (int i = tid; i < 10 * 17; i += 256) {
                int r = i / 17, u = i - r * 17;
                const float* srow = sp + (size_t)(h0 + r) * P2W + w0;
                if (u == 0) cp8(smem_u32(&s_x[xb2][r * C2_XSTR + 2]), srow + 2);
                else        cp16(smem_u32(&s_x[xb2][r * C2_XSTR + 4 * u]), srow + 4 * u);
            }
            CP_COMMIT();
            CP_WAIT1();
        } else {
            CP_WAIT0();
        }
        __syncthreads();

        {
            // xin[d] at cl = 8*c8 + 2 + d, d = 0..9 (input cols wb-1 .. wb+8)
            const float* xp = &s_x[s & 1][row * C2_XSTR + 8 * c8 + 2];
            const float* wcb = &s_w[(s >> 2) & 1][((s & 3) * TOPK + cog * 8) * 24];
            #pragma unroll
            for (int r = 0; r < 3; r++) {
                const float* rp = xp + r * C2_XSTR;
                float2 F  = *(const float2*)(rp);       // xin[0,1]
                float4 A  = *(const float4*)(rp + 2);   // xin[2..5]
                float4 Bv = *(const float4*)(rp + 6);   // xin[6..9]
                u64 Q[9];
                Q[0] = pk2(F.x, F.y);  Q[1] = pk2(F.y, A.x);  Q[2] = pk2(A.x, A.y);
                Q[3] = pk2(A.y, A.z);  Q[4] = pk2(A.z, A.w);  Q[5] = pk2(A.w, Bv.x);
                Q[6] = pk2(Bv.x, Bv.y); Q[7] = pk2(Bv.y, Bv.z); Q[8] = pk2(Bv.z, Bv.w);
                #pragma unroll
                for (int j = 0; j < 8; j++) {
                    const u64* wp = (const u64*)(wcb + j * 24 + r * 8);
                    ulonglong2 qq = *(const ulonglong2*)wp;
                    u64 q2 = wp[2];
                    #pragma unroll
                    for (int m = 0; m < 4; m++) {
                        fma2(acc[j][m], Q[2 * m],     qq.x);
                        fma2(acc[j][m], Q[2 * m + 1], qq.y);
                        fma2(acc[j][m], Q[2 * m + 2], q2);
                    }
                }
            }
        }
        __syncthreads();
    }

    const int h = h0 + row, w = w0 + 8 * c8;
    #pragma unroll
    for (int j = 0; j < 8; j++) {
        int co = cog * 8 + j;
        float g = s_gv[co];
        int c = s_idx2[co];
        float* base = &out[((size_t)(b * COUT + c) * OH + h) * OW + w];
        float4 id0 = *(const float4*)base;
        float4 id1 = *(const float4*)(base + 4);
        float v[8];
        #pragma unroll
        for (int m = 0; m < 4; m++) upk2(acc[j][m], v[2 * m], v[2 * m + 1]);
        float4 o0, o1;
        o0.x = leaky(leaky(v[0] * g) + id0.x);
        o0.y = leaky(leaky(v[1] * g) + id0.y);
        o0.z = leaky(leaky(v[2] * g) + id0.z);
        o0.w = leaky(leaky(v[3] * g) + id0.w);
        o1.x = leaky(leaky(v[4] * g) + id1.x);
        o1.y = leaky(leaky(v[5] * g) + id1.y);
        o1.z = leaky(leaky(v[6] * g) + id1.z);
        o1.w = leaky(leaky(v[7] * g) + id1.w);
        *(float4*)base = o0;
        *(float4*)(base + 4) = o1;
    }
}

// ============================================================================
extern "C" void kernel_launch(void* const* d_in, const int* in_sizes, int n_in,
                              void* d_out, int out_size) {
    const float* x     = (const float*)d_in[0];
    const float* emb   = (const float*)d_in[1];
    const float* w1    = (const float*)d_in[2];
    const float* w2    = (const float*)d_in[3];
    const float* dsw   = (const float*)d_in[4];
    const float* gam   = (const float*)d_in[5];
    const float* bet   = (const float*)d_in[6];
    const float* g1w   = (const float*)d_in[7];
    const float* g1b   = (const float*)d_in[8];
    const float* g2w   = (const float*)d_in[9];
    const float* g2b   = (const float*)d_in[10];
    float* out = (float*)d_out;

    gate_kernel<<<dim3(BATCH, 2), 128>>>(emb, g1w, g1b, g2w, g2b, out);
    ds_kernel<<<dim3(36, 4, BATCH), 256>>>(x, dsw, gam, bet, out);
    conv1_kernel<<<dim3(36, BATCH), 256>>>(x, w1);
    conv2_kernel<<<dim3(36, BATCH), 256>>>(w2, out);
}

// round 7
// speedup vs baseline: 1.0714x; 1.0708x over previous
#include <cuda_runtime.h>
#include <math.h>

#define BATCH 8
#define CIN   64
#define COUT  128
#define EDIM  128
#define HIN   192
#define WIN   384
#define OH    96
#define OW    192
#define TOPK  32
#define OUT6_SIZE (BATCH*COUT*OH*OW)

// padded conv1->conv2 buffer: out row h at pr=h+1 (98 rows), out col w at pc=w+3 (200 cols)
#define P2H 98
#define P2W 200

typedef unsigned long long u64;

__device__ float d_out2p[BATCH*TOPK*P2H*P2W];
__device__ int   d_idx1[BATCH*TOPK];
__device__ float d_gv1 [BATCH*TOPK];
__device__ int   d_idx2[BATCH*TOPK];
__device__ float d_gv2 [BATCH*TOPK];
__device__ int   d_slot2[BATCH*COUT];

__device__ __forceinline__ float leaky(float v) { return v >= 0.f ? v : 0.2f * v; }

__device__ __forceinline__ u64 pk2(float lo, float hi) {
    u64 r; asm("mov.b64 %0, {%1, %2};" : "=l"(r) : "f"(lo), "f"(hi)); return r;
}
__device__ __forceinline__ void upk2(u64 v, float& lo, float& hi) {
    asm("mov.b64 {%0, %1}, %2;" : "=f"(lo), "=f"(hi) : "l"(v));
}
__device__ __forceinline__ void fma2(u64& d, u64 a, u64 b) {
    asm("fma.rn.f32x2 %0, %1, %2, %0;" : "+l"(d) : "l"(a), "l"(b));
}
__device__ __forceinline__ unsigned smem_u32(const void* p) {
    return (unsigned)__cvta_generic_to_shared(p);
}
__device__ __forceinline__ void cp4(unsigned dst, const void* src, int sz) {
    asm volatile("cp.async.ca.shared.global [%0], [%1], 4, %2;" :: "r"(dst), "l"(src), "r"(sz));
}
__device__ __forceinline__ void cp8(unsigned dst, const void* src) {
    asm volatile("cp.async.ca.shared.global [%0], [%1], 8;" :: "r"(dst), "l"(src));
}
__device__ __forceinline__ void cp16(unsigned dst, const void* src) {
    asm volatile("cp.async.ca.shared.global [%0], [%1], 16;" :: "r"(dst), "l"(src));
}
__device__ __forceinline__ void cp16s(unsigned dst, const void* src, int sz) {
    asm volatile("cp.async.ca.shared.global [%0], [%1], 16, %2;" :: "r"(dst), "l"(src), "r"(sz));
}
#define CP_COMMIT() asm volatile("cp.async.commit_group;")
#define CP_WAIT1()  asm volatile("cp.async.wait_group 1;")
#define CP_WAIT0()  asm volatile("cp.async.wait_group 0;")

// ============================================================================
// Gate
// ============================================================================
__global__ void gate_kernel(const float* __restrict__ emb,
                            const float* __restrict__ g1w, const float* __restrict__ g1b,
                            const float* __restrict__ g2w, const float* __restrict__ g2b,
                            float* __restrict__ out) {
    const int b    = blockIdx.x;
    const int gate = blockIdx.y;
    const int c    = threadIdx.x;
    const float* gw = (gate == 0) ? g1w : g2w;
    const float* gb = (gate == 0) ? g1b : g2b;

    __shared__ float s_emb[EDIM];
    __shared__ float s_log[COUT];
    __shared__ float s_exp[COUT];

    s_emb[c] = emb[b * EDIM + c];
    __syncthreads();

    float l = gb[c];
    #pragma unroll 8
    for (int e = 0; e < EDIM; e++) l += s_emb[e] * gw[e * COUT + c];
    s_log[c] = l;
    __syncthreads();

    int rank = 0;
    float m = -1e30f;
    for (int j = 0; j < COUT; j++) {
        float lj = s_log[j];
        if (lj > l || (lj == l && j < c)) rank++;
        if (lj > m) m = lj;
    }
    bool sel = (rank < TOPK);
    float ev = sel ? expf(l - m) : 0.0f;
    s_exp[c] = ev;
    __syncthreads();

    float s = 0.f;
    for (int j = 0; j < COUT; j++) s += s_exp[j];
    float gv = ev / s;

    out[OUT6_SIZE + gate * (BATCH * COUT) + b * COUT + c] = gv;

    if (gate == 0) {
        if (sel) { d_idx1[b * TOPK + rank] = c; d_gv1[b * TOPK + rank] = gv; }
    } else {
        d_slot2[b * COUT + c] = sel ? rank : -1;
        if (sel) { d_idx2[b * TOPK + rank] = c; d_gv2[b * TOPK + rank] = gv; }
    }
}

// ============================================================================
// ds: all 128 co per block, x staged ONCE compact. Tile 8x16 px.
// Thread: 8 px x 8 co. grid (144, 8). Dynamic smem ~66KB.
// Gate2-selected channels write RAW ident (conv2 fuses add+leaky).
// ============================================================================
#define DS_SMEM ((8192 + 8192 + 384) * 4)
__global__ void __launch_bounds__(256, 2) ds_kernel(const float* __restrict__ x,
                                                    const float* __restrict__ dsw,
                                                    const float* __restrict__ gamma,
                                                    const float* __restrict__ beta,
                                                    float* __restrict__ out) {
    extern __shared__ __align__(16) float dsm[];
    float* s_xc    = dsm;              // [64][128] compact px-major
    float* s_wt    = dsm + 8192;       // [64][128] transposed weights
    float* s_scale = dsm + 16384;
    float* s_betav = s_scale + 128;
    int*   s_slot  = (int*)(s_betav + 128);

    const int b  = blockIdx.y;
    const int h0 = (blockIdx.x / 12) * 8;
    const int w0 = (blockIdx.x % 12) * 16;
    const int tid = threadIdx.x;
    const int po  = tid >> 4;          // px octet 0..15
    const int cg  = tid & 15;          // co octet 0..15

    const float* xb = x + (size_t)b * CIN * HIN * WIN;
    #pragma unroll 8
    for (int k = 0; k < 32; k++) {
        int i = tid + k * 256;
        int ci = i >> 7, p = i & 127, r = (p >> 4), j = p & 15;
        cp4(smem_u32(&s_xc[i]), xb + (size_t)ci * HIN * WIN + (2 * (h0 + r)) * WIN + 2 * (w0 + j), 4);
    }
    #pragma unroll 8
    for (int k = 0; k < 32; k++) {
        int i = tid + k * 256;
        int co = i >> 6, ci = i & 63;
        cp4(smem_u32(&s_wt[ci * 128 + co]), dsw + i, 4);
    }
    if (tid < 128) {
        s_scale[tid] = gamma[tid] * rsqrtf(1.0f + 1e-5f);
        s_betav[tid] = beta[tid];
        s_slot[tid]  = d_slot2[b * COUT + tid];
    }
    CP_COMMIT(); CP_WAIT0();
    __syncthreads();

    u64 acc[8][4];
    #pragma unroll
    for (int c = 0; c < 8; c++)
        #pragma unroll
        for (int m = 0; m < 4; m++) acc[c][m] = 0ull;

    #pragma unroll 4
    for (int ci = 0; ci < 64; ci++) {
        const ulonglong2* xq = (const ulonglong2*)&s_xc[ci * 128 + 8 * po];
        ulonglong2 X0 = xq[0], X1 = xq[1];
        const float4* wq = (const float4*)&s_wt[ci * 128 + 8 * cg];
        float4 wa = wq[0], wb2 = wq[1];
        u64 W[8];
        W[0] = pk2(wa.x, wa.x);  W[1] = pk2(wa.y, wa.y);
        W[2] = pk2(wa.z, wa.z);  W[3] = pk2(wa.w, wa.w);
        W[4] = pk2(wb2.x, wb2.x); W[5] = pk2(wb2.y, wb2.y);
        W[6] = pk2(wb2.z, wb2.z); W[7] = pk2(wb2.w, wb2.w);
        #pragma unroll
        for (int c = 0; c < 8; c++) {
            fma2(acc[c][0], X0.x, W[c]);
            fma2(acc[c][1], X0.y, W[c]);
            fma2(acc[c][2], X1.x, W[c]);
            fma2(acc[c][3], X1.y, W[c]);
        }
    }

    const int hr  = h0 + (po >> 1);
    const int wc0 = w0 + (po & 1) * 8;
    #pragma unroll
    for (int c = 0; c < 8; c++) {
        int co = 8 * cg + c;
        float v[8];
        #pragma unroll
        for (int m = 0; m < 4; m++) upk2(acc[c][m], v[2 * m], v[2 * m + 1]);
        float sc = s_scale[co], be = s_betav[co];
        #pragma unroll
        for (int k = 0; k < 8; k++) v[k] = v[k] * sc + be;
        if (s_slot[co] < 0) {
            #pragma unroll
            for (int k = 0; k < 8; k++) v[k] = leaky(v[k]);
        }
        float* base = &out[((size_t)(b * COUT + co) * OH + hr) * OW + wc0];
        *(float4*)base       = make_float4(v[0], v[1], v[2], v[3]);
        *(float4*)(base + 4) = make_float4(v[4], v[5], v[6], v[7]);
    }
}

// ============================================================================
// conv1: 3x3 s2 p1, 32 gated channels. cp16 staging (132 cols from 2w0-4).
// Thread: 8 co x 8 px. grid (36, BATCH).
// ============================================================================
#define C1_XSTR 132
__global__ void __launch_bounds__(256, 2) conv1_kernel(const float* __restrict__ x,
                                                       const float* __restrict__ w1) {
    const int b = blockIdx.y, tile = blockIdx.x;
    const int h0 = (tile / 3) * 8, w0 = (tile % 3) * 64;
    const int tid = threadIdx.x;
    const int cog = tid >> 6;
    const int t   = tid & 63;
    const int row = t >> 3;
    const int c8  = t & 7;

    __shared__ int   s_idx[TOPK];
    __shared__ float s_gv[TOPK];
    __shared__ __align__(16) float s_w[2][4 * TOPK * 24];   // 24.6 KB
    __shared__ __align__(16) float s_x[2][17 * C1_XSTR];    // 17.9 KB

    if (tid < TOPK) { s_idx[tid] = d_idx1[b * TOPK + tid]; s_gv[tid] = d_gv1[b * TOPK + tid]; }
    __syncthreads();

    u64 acc[8][4];
    #pragma unroll
    for (int i = 0; i < 8; i++)
        #pragma unroll
        for (int m = 0; m < 4; m++) acc[i][m] = 0ull;

    // prologue
    {
        for (int i = tid; i < 4 * TOPK * 9; i += 256) {
            int ci_l = i / (TOPK * 9);
            int r = i - ci_l * (TOPK * 9);
            int co = r / 9, k = r - co * 9;
            const float* src = w1 + (s_idx[co] * CIN + ci_l) * 9 + k;
            unsigned dst = smem_u32(&s_w[0][(ci_l * TOPK + co) * 24 + (k / 3) * 8 + (k % 3) * 2]);
            cp4(dst, src, 4); cp4(dst + 4, src, 4);
        }
        const float* sp = x + (size_t)(b * CIN + 0) * HIN * WIN;
        for (int i = tid; i < 561; i += 256) {
            int r = i / 33, u = i - r * 33;
            int gr = 2 * h0 - 1 + r, gc = 2 * w0 - 4 + 4 * u;
            int ok = (gr >= 0 && gc >= 0) ? 16 : 0;
            cp16s(smem_u32(&s_x[0][r * C1_XSTR + 4 * u]), sp + (size_t)gr * WIN + gc, ok);
        }
        CP_COMMIT();
    }

    for (int s = 0; s < CIN; s++) {
        if (s + 1 < CIN) {
            const int sn = s + 1;
            if ((sn & 3) == 0) {
                const int chunk = sn >> 2, wb = chunk & 1;
                for (int i = tid; i < 4 * TOPK * 9; i += 256) {
                    int ci_l = i / (TOPK * 9);
                    int r = i - ci_l * (TOPK * 9);
                    int co = r / 9, k = r - co * 9;
                    const float* src = w1 + (s_idx[co] * CIN + chunk * 4 + ci_l) * 9 + k;
                    unsigned dst = smem_u32(&s_w[wb][(ci_l * TOPK + co) * 24 + (k / 3) * 8 + (k % 3) * 2]);
                    cp4(dst, src, 4); cp4(dst + 4, src, 4);
                }
            }
            const float* sp = x + (size_t)(b * CIN + sn) * HIN * WIN;
            const int xb2 = sn & 1;
            for (int i = tid; i < 561; i += 256) {
                int r = i / 33, u = i - r * 33;
                int gr = 2 * h0 - 1 + r, gc = 2 * w0 - 4 + 4 * u;
                int ok = (gr >= 0 && gc >= 0) ? 16 : 0;
                cp16s(smem_u32(&s_x[xb2][r * C1_XSTR + 4 * u]), sp + (size_t)gr * WIN + gc, ok);
            }
            CP_COMMIT();
            CP_WAIT1();
        } else {
            CP_WAIT0();
        }
        __syncthreads();

        {
            // base col 2w0+16c8-1 lives at cl = 16c8+3
            const float* xp = &s_x[s & 1][(2 * row) * C1_XSTR + 16 * c8];
            const float* wcb = &s_w[(s >> 2) & 1][((s & 3) * TOPK + cog * 8) * 24];
            #pragma unroll
            for (int r = 0; r < 3; r++) {
                const float* rp = xp + r * C1_XSTR;
                float  e  = rp[3];
                float4 A0 = *(const float4*)(rp + 4);
                float4 A1 = *(const float4*)(rp + 8);
                float4 A2 = *(const float4*)(rp + 12);
                float4 A3 = *(const float4*)(rp + 16);
                u64 S[4][3];
                S[0][0] = pk2(e,    A0.y); S[0][1] = pk2(A0.x, A0.z); S[0][2] = pk2(A0.y, A0.w);
                S[1][0] = pk2(A0.w, A1.y); S[1][1] = pk2(A1.x, A1.z); S[1][2] = pk2(A1.y, A1.w);
                S[2][0] = pk2(A1.w, A2.y); S[2][1] = pk2(A2.x, A2.z); S[2][2] = pk2(A2.y, A2.w);
                S[3][0] = pk2(A2.w, A3.y); S[3][1] = pk2(A3.x, A3.z); S[3][2] = pk2(A3.y, A3.w);
                #pragma unroll
                for (int j = 0; j < 8; j++) {
                    const u64* wp = (const u64*)(wcb + j * 24 + r * 8);
                    ulonglong2 qq = *(const ulonglong2*)wp;
                    u64 q2 = wp[2];
                    #pragma unroll
                    for (int m = 0; m < 4; m++) {
                        fma2(acc[j][m], S[m][0], qq.x);
                        fma2(acc[j][m], S[m][1], qq.y);
                        fma2(acc[j][m], S[m][2], q2);
                    }
                }
            }
        }
        __syncthreads();
    }

    const int h = h0 + row, w = w0 + 8 * c8;
    #pragma unroll
    for (int j = 0; j < 8; j++) {
        int co = cog * 8 + j;
        float g = s_gv[co];
        float* base = &d_out2p[((size_t)(b * TOPK + co) * P2H + h + 1) * P2W + (w + 3)];
        #pragma unroll
        for (int m = 0; m < 4; m++) {
            float lo, hi; upk2(acc[j][m], lo, hi);
            base[2 * m]     = leaky(lo * g);
            base[2 * m + 1] = leaky(hi * g);
        }
    }
}

// ============================================================================
// conv2: unchanged from R5/R6 (fused epilogue: leaky(leaky(conv*g2)+ident)).
// ============================================================================
#define C2_XSTR 72
__global__ void __launch_bounds__(256, 2) conv2_kernel(const float* __restrict__ w2,
                                                       float* __restrict__ out) {
    const int b = blockIdx.y, tile = blockIdx.x;
    const int h0 = (tile / 3) * 8, w0 = (tile % 3) * 64;
    const int tid = threadIdx.x;
    const int cog = tid >> 6;
    const int t   = tid & 63;
    const int row = t >> 3;
    const int c8  = t & 7;

    __shared__ int   s_idx1[TOPK];
    __shared__ int   s_idx2[TOPK];
    __shared__ float s_gv[TOPK];
    __shared__ __align__(16) float s_w[2][4 * TOPK * 24];
    __shared__ __align__(16) float s_x[2][10 * C2_XSTR];

    if (tid < TOPK) {
        s_idx1[tid] = d_idx1[b * TOPK + tid];
        s_idx2[tid] = d_idx2[b * TOPK + tid];
        s_gv[tid]   = d_gv2[b * TOPK + tid];
    }
    __syncthreads();

    u64 acc[8][4];
    #pragma unroll
    for (int i = 0; i < 8; i++)
        #pragma unroll
        for (int m = 0; m < 4; m++) acc[i][m] = 0ull;

    {
        for (int i = tid; i < 4 * TOPK * 9; i += 256) {
            int ci_l = i / (TOPK * 9);
            int r = i - ci_l * (TOPK * 9);
            int co = r / 9, k = r - co * 9;
            const float* src = w2 + (s_idx2[co] * COUT + s_idx1[ci_l]) * 9 + k;
            unsigned dst = smem_u32(&s_w[0][(ci_l * TOPK + co) * 24 + (k / 3) * 8 + (k % 3) * 2]);
            cp4(dst, src, 4); cp4(dst + 4, src, 4);
        }
        const float* sp = d_out2p + (size_t)(b * TOPK + 0) * P2H * P2W;
        for (int i = tid; i < 10 * 17; i += 256) {
            int r = i / 17, u = i - r * 17;
            const float* srow = sp + (size_t)(h0 + r) * P2W + w0;
            if (u == 0) cp8(smem_u32(&s_x[0][r * C2_XSTR + 2]), srow + 2);
            else        cp16(smem_u32(&s_x[0][r * C2_XSTR + 4 * u]), srow + 4 * u);
        }
        CP_COMMIT();
    }

    for (int s = 0; s < TOPK; s++) {
        if (s + 1 < TOPK) {
            const int sn = s + 1;
            if ((sn & 3) == 0) {
                const int chunk = sn >> 2, wb = chunk & 1;
                for (int i = tid; i < 4 * TOPK * 9; i += 256) {
                    int ci_l = i / (TOPK * 9);
                    int r = i - ci_l * (TOPK * 9);
                    int co = r / 9, k = r - co * 9;
                    const float* src = w2 + (s_idx2[co] * COUT + s_idx1[chunk * 4 + ci_l]) * 9 + k;
                    unsigned dst = smem_u32(&s_w[wb][(ci_l * TOPK + co) * 24 + (k / 3) * 8 + (k % 3) * 2]);
                    cp4(dst, src, 4); cp4(dst + 4, src, 4);
                }
            }
            const float* sp = d_out2p + (size_t)(b * TOPK + sn) * P2H * P2W;
            const int xb2 = sn & 1;
            for (int i = tid; i < 10 * 17; i += 256) {
                int r = i / 17, u = i - r * 17;
                const float* srow = sp + (size_t)(h0 + r) * P2W + w0;
                if (u == 0) cp8(smem_u32(&s_x[xb2][r * C2_XSTR + 2]), srow + 2);
                else        cp16(smem_u32(&s_x[xb2][r * C2_XSTR + 4 * u]), srow + 4 * u);
            }
            CP_COMMIT();
            CP_WAIT1();
        } else {
            CP_WAIT0();
        }
        __syncthreads();

        {
            const float* xp = &s_x[s & 1][row * C2_XSTR + 8 * c8 + 2];
            const float* wcb = &s_w[(s >> 2) & 1][((s & 3) * TOPK + cog * 8) * 24];
            #pragma unroll
            for (int r = 0; r < 3; r++) {
                const float* rp = xp + r * C2_XSTR;
                float2 F  = *(const float2*)(rp);
                float4 A  = *(const float4*)(rp + 2);
                float4 Bv = *(const float4*)(rp + 6);
                u64 Q[9];
                Q[0] = pk2(F.x, F.y);   Q[1] = pk2(F.y, A.x);   Q[2] = pk2(A.x, A.y);
                Q[3] = pk2(A.y, A.z);   Q[4] = pk2(A.z, A.w);   Q[5] = pk2(A.w, Bv.x);
                Q[6] = pk2(Bv.x, Bv.y); Q[7] = pk2(Bv.y, Bv.z); Q[8] = pk2(Bv.z, Bv.w);
                #pragma unroll
                for (int j = 0; j < 8; j++) {
                    const u64* wp = (const u64*)(wcb + j * 24 + r * 8);
                    ulonglong2 qq = *(const ulonglong2*)wp;
                    u64 q2 = wp[2];
                    #pragma unroll
                    for (int m = 0; m < 4; m++) {
                        fma2(acc[j][m], Q[2 * m],     qq.x);
                        fma2(acc[j][m], Q[2 * m + 1], qq.y);
                        fma2(acc[j][m], Q[2 * m + 2], q2);
                    }
                }
            }
        }
        __syncthreads();
    }

    const int h = h0 + row, w = w0 + 8 * c8;
    #pragma unroll
    for (int j = 0; j < 8; j++) {
        int co = cog * 8 + j;
        float g = s_gv[co];
        int c = s_idx2[co];
        float* base = &out[((size_t)(b * COUT + c) * OH + h) * OW + w];
        float4 id0 = *(const float4*)base;
        float4 id1 = *(const float4*)(base + 4);
        float v[8];
        #pragma unroll
        for (int m = 0; m < 4; m++) upk2(acc[j][m], v[2 * m], v[2 * m + 1]);
        float4 o0, o1;
        o0.x = leaky(leaky(v[0] * g) + id0.x);
        o0.y = leaky(leaky(v[1] * g) + id0.y);
        o0.z = leaky(leaky(v[2] * g) + id0.z);
        o0.w = leaky(leaky(v[3] * g) + id0.w);
        o1.x = leaky(leaky(v[4] * g) + id1.x);
        o1.y = leaky(leaky(v[5] * g) + id1.y);
        o1.z = leaky(leaky(v[6] * g) + id1.z);
        o1.w = leaky(leaky(v[7] * g) + id1.w);
        *(float4*)base = o0;
        *(float4*)(base + 4) = o1;
    }
}

// ============================================================================
extern "C" void kernel_launch(void* const* d_in, const int* in_sizes, int n_in,
                              void* d_out, int out_size) {
    const float* x     = (const float*)d_in[0];
    const float* emb   = (const float*)d_in[1];
    const float* w1    = (const float*)d_in[2];
    const float* w2    = (const float*)d_in[3];
    const float* dsw   = (const float*)d_in[4];
    const float* gam   = (const float*)d_in[5];
    const float* bet   = (const float*)d_in[6];
    const float* g1w   = (const float*)d_in[7];
    const float* g1b   = (const float*)d_in[8];
    const float* g2w   = (const float*)d_in[9];
    const float* g2b   = (const float*)d_in[10];
    float* out = (float*)d_out;

    cudaFuncSetAttribute(ds_kernel, cudaFuncAttributeMaxDynamicSharedMemorySize, DS_SMEM);

    gate_kernel<<<dim3(BATCH, 2), 128>>>(emb, g1w, g1b, g2w, g2b, out);
    ds_kernel<<<dim3(144, BATCH), 256, DS_SMEM>>>(x, dsw, gam, bet, out);
    conv1_kernel<<<dim3(36, BATCH), 256>>>(x, w1);
    conv2_kernel<<<dim3(36, BATCH), 256>>>(w2, out);
}

// round 8
// speedup vs baseline: 1.1036x; 1.0301x over previous
#include <cuda_runtime.h>
#include <math.h>

#define BATCH 8
#define CIN   64
#define COUT  128
#define EDIM  128
#define HIN   192
#define WIN   384
#define OH    96
#define OW    192
#define TOPK  32
#define OUT6_SIZE (BATCH*COUT*OH*OW)

// padded conv1->conv2 buffer: out row h at pr=h+1 (98 rows), out col w at pc=w+4 (204 cols)
#define P2H 98
#define P2W 204

typedef unsigned long long u64;

__device__ float d_out2p[BATCH*TOPK*P2H*P2W];
__device__ int   d_idx1[BATCH*TOPK];
__device__ float d_gv1 [BATCH*TOPK];
__device__ int   d_idx2[BATCH*TOPK];
__device__ float d_gv2 [BATCH*TOPK];
__device__ int   d_slot2[BATCH*COUT];

__device__ __forceinline__ float leaky(float v) { return v >= 0.f ? v : 0.2f * v; }

__device__ __forceinline__ u64 pk2(float lo, float hi) {
    u64 r; asm("mov.b64 %0, {%1, %2};" : "=l"(r) : "f"(lo), "f"(hi)); return r;
}
__device__ __forceinline__ void upk2(u64 v, float& lo, float& hi) {
    asm("mov.b64 {%0, %1}, %2;" : "=f"(lo), "=f"(hi) : "l"(v));
}
__device__ __forceinline__ void fma2(u64& d, u64 a, u64 b) {
    asm("fma.rn.f32x2 %0, %1, %2, %0;" : "+l"(d) : "l"(a), "l"(b));
}
__device__ __forceinline__ unsigned smem_u32(const void* p) {
    return (unsigned)__cvta_generic_to_shared(p);
}
__device__ __forceinline__ void cp4(unsigned dst, const void* src, int sz) {
    asm volatile("cp.async.ca.shared.global [%0], [%1], 4, %2;" :: "r"(dst), "l"(src), "r"(sz));
}
__device__ __forceinline__ void cp16(unsigned dst, const void* src) {
    asm volatile("cp.async.ca.shared.global [%0], [%1], 16;" :: "r"(dst), "l"(src));
}
__device__ __forceinline__ void cp16s(unsigned dst, const void* src, int sz) {
    asm volatile("cp.async.ca.shared.global [%0], [%1], 16, %2;" :: "r"(dst), "l"(src), "r"(sz));
}
#define CP_COMMIT() asm volatile("cp.async.commit_group;")
#define CP_WAIT1()  asm volatile("cp.async.wait_group 1;")
#define CP_WAIT0()  asm volatile("cp.async.wait_group 0;")

// ============================================================================
// Gate
// ============================================================================
__global__ void gate_kernel(const float* __restrict__ emb,
                            const float* __restrict__ g1w, const float* __restrict__ g1b,
                            const float* __restrict__ g2w, const float* __restrict__ g2b,
                            float* __restrict__ out) {
    const int b    = blockIdx.x;
    const int gate = blockIdx.y;
    const int c    = threadIdx.x;
    const float* gw = (gate == 0) ? g1w : g2w;
    const float* gb = (gate == 0) ? g1b : g2b;

    __shared__ float s_emb[EDIM];
    __shared__ float s_log[COUT];
    __shared__ float s_exp[COUT];

    s_emb[c] = emb[b * EDIM + c];
    __syncthreads();

    float l = gb[c];
    #pragma unroll 8
    for (int e = 0; e < EDIM; e++) l += s_emb[e] * gw[e * COUT + c];
    s_log[c] = l;
    __syncthreads();

    int rank = 0;
    float m = -1e30f;
    for (int j = 0; j < COUT; j++) {
        float lj = s_log[j];
        if (lj > l || (lj == l && j < c)) rank++;
        if (lj > m) m = lj;
    }
    bool sel = (rank < TOPK);
    float ev = sel ? expf(l - m) : 0.0f;
    s_exp[c] = ev;
    __syncthreads();

    float s = 0.f;
    for (int j = 0; j < COUT; j++) s += s_exp[j];
    float gv = ev / s;

    out[OUT6_SIZE + gate * (BATCH * COUT) + b * COUT + c] = gv;

    if (gate == 0) {
        if (sel) { d_idx1[b * TOPK + rank] = c; d_gv1[b * TOPK + rank] = gv; }
    } else {
        d_slot2[b * COUT + c] = sel ? rank : -1;
        if (sel) { d_idx2[b * TOPK + rank] = c; d_gv2[b * TOPK + rank] = gv; }
    }
}

// ============================================================================
// ds: all 128 co per block, x staged once. Tile 8x16 px. (unchanged from R7)
// ============================================================================
#define DS_SMEM ((8192 + 8192 + 384) * 4)
__global__ void __launch_bounds__(256, 2) ds_kernel(const float* __restrict__ x,
                                                    const float* __restrict__ dsw,
                                                    const float* __restrict__ gamma,
                                                    const float* __restrict__ beta,
                                                    float* __restrict__ out) {
    extern __shared__ __align__(16) float dsm[];
    float* s_xc    = dsm;
    float* s_wt    = dsm + 8192;
    float* s_scale = dsm + 16384;
    float* s_betav = s_scale + 128;
    int*   s_slot  = (int*)(s_betav + 128);

    const int b  = blockIdx.y;
    const int h0 = (blockIdx.x / 12) * 8;
    const int w0 = (blockIdx.x % 12) * 16;
    const int tid = threadIdx.x;
    const int po  = tid >> 4;
    const int cg  = tid & 15;

    const float* xb = x + (size_t)b * CIN * HIN * WIN;
    #pragma unroll 8
    for (int k = 0; k < 32; k++) {
        int i = tid + k * 256;
        int ci = i >> 7, p = i & 127, r = (p >> 4), j = p & 15;
        cp4(smem_u32(&s_xc[i]), xb + (size_t)ci * HIN * WIN + (2 * (h0 + r)) * WIN + 2 * (w0 + j), 4);
    }
    #pragma unroll 8
    for (int k = 0; k < 32; k++) {
        int i = tid + k * 256;
        int co = i >> 6, ci = i & 63;
        cp4(smem_u32(&s_wt[ci * 128 + co]), dsw + i, 4);
    }
    if (tid < 128) {
        s_scale[tid] = gamma[tid] * rsqrtf(1.0f + 1e-5f);
        s_betav[tid] = beta[tid];
        s_slot[tid]  = d_slot2[b * COUT + tid];
    }
    CP_COMMIT(); CP_WAIT0();
    __syncthreads();

    u64 acc[8][4];
    #pragma unroll
    for (int c = 0; c < 8; c++)
        #pragma unroll
        for (int m = 0; m < 4; m++) acc[c][m] = 0ull;

    #pragma unroll 4
    for (int ci = 0; ci < 64; ci++) {
        const ulonglong2* xq = (const ulonglong2*)&s_xc[ci * 128 + 8 * po];
        ulonglong2 X0 = xq[0], X1 = xq[1];
        const float4* wq = (const float4*)&s_wt[ci * 128 + 8 * cg];
        float4 wa = wq[0], wb2 = wq[1];
        u64 W[8];
        W[0] = pk2(wa.x, wa.x);   W[1] = pk2(wa.y, wa.y);
        W[2] = pk2(wa.z, wa.z);   W[3] = pk2(wa.w, wa.w);
        W[4] = pk2(wb2.x, wb2.x); W[5] = pk2(wb2.y, wb2.y);
        W[6] = pk2(wb2.z, wb2.z); W[7] = pk2(wb2.w, wb2.w);
        #pragma unroll
        for (int c = 0; c < 8; c++) {
            fma2(acc[c][0], X0.x, W[c]);
            fma2(acc[c][1], X0.y, W[c]);
            fma2(acc[c][2], X1.x, W[c]);
            fma2(acc[c][3], X1.y, W[c]);
        }
    }

    const int hr  = h0 + (po >> 1);
    const int wc0 = w0 + (po & 1) * 8;
    #pragma unroll
    for (int c = 0; c < 8; c++) {
        int co = 8 * cg + c;
        float v[8];
        #pragma unroll
        for (int m = 0; m < 4; m++) upk2(acc[c][m], v[2 * m], v[2 * m + 1]);
        float sc = s_scale[co], be = s_betav[co];
        #pragma unroll
        for (int k = 0; k < 8; k++) v[k] = v[k] * sc + be;
        if (s_slot[co] < 0) {
            #pragma unroll
            for (int k = 0; k < 8; k++) v[k] = leaky(v[k]);
        }
        float* base = &out[((size_t)(b * COUT + co) * OH + hr) * OW + wc0];
        *(float4*)base       = make_float4(v[0], v[1], v[2], v[3]);
        *(float4*)(base + 4) = make_float4(v[4], v[5], v[6], v[7]);
    }
}

// ============================================================================
// conv1: 3x3 s2 p1, 32 gated channels. Thread: 8 co x 4 px (low regs, 3 CTA).
// Tile 8x32 out px. grid (72, BATCH). s_x cols from 2w0-4, stride 68.
// ============================================================================
#define C1_XSTR 68
__global__ void __launch_bounds__(256, 3) conv1_kernel(const float* __restrict__ x,
                                                       const float* __restrict__ w1) {
    const int b = blockIdx.y, tile = blockIdx.x;
    const int h0 = (tile / 6) * 8, w0 = (tile % 6) * 32;
    const int tid = threadIdx.x;
    const int cog = tid >> 6;
    const int t   = tid & 63;
    const int row = t >> 3;
    const int c4  = t & 7;

    __shared__ int   s_idx[TOPK];
    __shared__ float s_gv[TOPK];
    __shared__ __align__(16) float s_w[2][4 * TOPK * 24];   // 24.6 KB
    __shared__ __align__(16) float s_x[2][17 * C1_XSTR];    // 9.2 KB

    if (tid < TOPK) { s_idx[tid] = d_idx1[b * TOPK + tid]; s_gv[tid] = d_gv1[b * TOPK + tid]; }
    __syncthreads();

    u64 acc[8][2];
    #pragma unroll
    for (int i = 0; i < 8; i++) { acc[i][0] = 0ull; acc[i][1] = 0ull; }

    // prologue
    {
        for (int i = tid; i < 4 * TOPK * 9; i += 256) {
            int ci_l = i / (TOPK * 9);
            int r = i - ci_l * (TOPK * 9);
            int co = r / 9, k = r - co * 9;
            const float* src = w1 + (s_idx[co] * CIN + ci_l) * 9 + k;
            unsigned dst = smem_u32(&s_w[0][(ci_l * TOPK + co) * 24 + (k / 3) * 8 + (k % 3) * 2]);
            cp4(dst, src, 4); cp4(dst + 4, src, 4);
        }
        const float* sp = x + (size_t)(b * CIN + 0) * HIN * WIN;
        for (int i = tid; i < 289; i += 256) {
            int r = i / 17, u = i - r * 17;
            int gr = 2 * h0 - 1 + r, gc = 2 * w0 - 4 + 4 * u;
            int ok = (gr >= 0 && gc >= 0) ? 16 : 0;
            cp16s(smem_u32(&s_x[0][r * C1_XSTR + 4 * u]), sp + (size_t)gr * WIN + gc, ok);
        }
        CP_COMMIT();
    }

    for (int s = 0; s < CIN; s++) {
        if (s + 1 < CIN) {
            const int sn = s + 1;
            if ((sn & 3) == 0) {
                const int chunk = sn >> 2, wb = chunk & 1;
                for (int i = tid; i < 4 * TOPK * 9; i += 256) {
                    int ci_l = i / (TOPK * 9);
                    int r = i - ci_l * (TOPK * 9);
                    int co = r / 9, k = r - co * 9;
                    const float* src = w1 + (s_idx[co] * CIN + chunk * 4 + ci_l) * 9 + k;
                    unsigned dst = smem_u32(&s_w[wb][(ci_l * TOPK + co) * 24 + (k / 3) * 8 + (k % 3) * 2]);
                    cp4(dst, src, 4); cp4(dst + 4, src, 4);
                }
            }
            const float* sp = x + (size_t)(b * CIN + sn) * HIN * WIN;
            const int xb2 = sn & 1;
            for (int i = tid; i < 289; i += 256) {
                int r = i / 17, u = i - r * 17;
                int gr = 2 * h0 - 1 + r, gc = 2 * w0 - 4 + 4 * u;
                int ok = (gr >= 0 && gc >= 0) ? 16 : 0;
                cp16s(smem_u32(&s_x[xb2][r * C1_XSTR + 4 * u]), sp + (size_t)gr * WIN + gc, ok);
            }
            CP_COMMIT();
            CP_WAIT1();
        } else {
            CP_WAIT0();
        }
        __syncthreads();

        {
            // p0..p8 at cl 8c4+3 .. 8c4+11 (input cols 2(w0+4c4)-1 .. +7)
            const float* xp = &s_x[s & 1][(2 * row) * C1_XSTR + 8 * c4];
            const float* wcb = &s_w[(s >> 2) & 1][((s & 3) * TOPK + cog * 8) * 24];
            #pragma unroll
            for (int r = 0; r < 3; r++) {
                const float* rp = xp + r * C1_XSTR;
                float  p0 = rp[3];
                float4 A0 = *(const float4*)(rp + 4);
                float4 A1 = *(const float4*)(rp + 8);
                u64 S00 = pk2(p0,   A0.y);
                u64 S01 = pk2(A0.x, A0.z);
                u64 S02 = pk2(A0.y, A0.w);
                u64 S10 = pk2(A0.w, A1.y);
                u64 S11 = pk2(A1.x, A1.z);
                u64 S12 = pk2(A1.y, A1.w);
                #pragma unroll
                for (int j = 0; j < 8; j++) {
                    const u64* wp = (const u64*)(wcb + j * 24 + r * 8);
                    ulonglong2 qq = *(const ulonglong2*)wp;
                    u64 q2 = wp[2];
                    fma2(acc[j][0], S00, qq.x);
                    fma2(acc[j][0], S01, qq.y);
                    fma2(acc[j][0], S02, q2);
                    fma2(acc[j][1], S10, qq.x);
                    fma2(acc[j][1], S11, qq.y);
                    fma2(acc[j][1], S12, q2);
                }
            }
        }
        __syncthreads();
    }

    const int h = h0 + row, w = w0 + 4 * c4;
    #pragma unroll
    for (int j = 0; j < 8; j++) {
        int co = cog * 8 + j;
        float g = s_gv[co];
        float v0, v1, v2, v3;
        upk2(acc[j][0], v0, v1);
        upk2(acc[j][1], v2, v3);
        float4 o;
        o.x = leaky(v0 * g); o.y = leaky(v1 * g);
        o.z = leaky(v2 * g); o.w = leaky(v3 * g);
        *(float4*)&d_out2p[((size_t)(b * TOPK + co) * P2H + h + 1) * P2W + (w + 4)] = o;
    }
}

// ============================================================================
// conv2: 3x3 s1 p1, 32 in -> 32 gated out, fused leaky(leaky(conv*g2)+ident).
// Thread: 8 co x 4 px. Tile 8x32. grid (72, BATCH). s_x stride 40, from pc w0.
// ============================================================================
#define C2_XSTR 40
__global__ void __launch_bounds__(256, 3) conv2_kernel(const float* __restrict__ w2,
                                                       float* __restrict__ out) {
    const int b = blockIdx.y, tile = blockIdx.x;
    const int h0 = (tile / 6) * 8, w0 = (tile % 6) * 32;
    const int tid = threadIdx.x;
    const int cog = tid >> 6;
    const int t   = tid & 63;
    const int row = t >> 3;
    const int c4  = t & 7;

    __shared__ int   s_idx1[TOPK];
    __shared__ int   s_idx2[TOPK];
    __shared__ float s_gv[TOPK];
    __shared__ __align__(16) float s_w[2][4 * TOPK * 24];   // 24.6 KB
    __shared__ __align__(16) float s_x[2][10 * C2_XSTR];    // 3.2 KB

    if (tid < TOPK) {
        s_idx1[tid] = d_idx1[b * TOPK + tid];
        s_idx2[tid] = d_idx2[b * TOPK + tid];
        s_gv[tid]   = d_gv2[b * TOPK + tid];
    }
    __syncthreads();

    u64 acc[8][2];
    #pragma unroll
    for (int i = 0; i < 8; i++) { acc[i][0] = 0ull; acc[i][1] = 0ull; }

    // prologue
    {
        for (int i = tid; i < 4 * TOPK * 9; i += 256) {
            int ci_l = i / (TOPK * 9);
            int r = i - ci_l * (TOPK * 9);
            int co = r / 9, k = r - co * 9;
            const float* src = w2 + (s_idx2[co] * COUT + s_idx1[ci_l]) * 9 + k;
            unsigned dst = smem_u32(&s_w[0][(ci_l * TOPK + co) * 24 + (k / 3) * 8 + (k % 3) * 2]);
            cp4(dst, src, 4); cp4(dst + 4, src, 4);
        }
        const float* sp = d_out2p + (size_t)(b * TOPK + 0) * P2H * P2W;
        for (int i = tid; i < 100; i += 256) {
            int r = i / 10, u = i - r * 10;
            cp16(smem_u32(&s_x[0][r * C2_XSTR + 4 * u]), sp + (size_t)(h0 + r) * P2W + w0 + 4 * u);
        }
        CP_COMMIT();
    }

    for (int s = 0; s < TOPK; s++) {
        if (s + 1 < TOPK) {
            const int sn = s + 1;
            if ((sn & 3) == 0) {
                const int chunk = sn >> 2, wb = chunk & 1;
                for (int i = tid; i < 4 * TOPK * 9; i += 256) {
                    int ci_l = i / (TOPK * 9);
                    int r = i - ci_l * (TOPK * 9);
                    int co = r / 9, k = r - co * 9;
                    const float* src = w2 + (s_idx2[co] * COUT + s_idx1[chunk * 4 + ci_l]) * 9 + k;
                    unsigned dst = smem_u32(&s_w[wb][(ci_l * TOPK + co) * 24 + (k / 3) * 8 + (k % 3) * 2]);
                    cp4(dst, src, 4); cp4(dst + 4, src, 4);
                }
            }
            const float* sp = d_out2p + (size_t)(b * TOPK + sn) * P2H * P2W;
            const int xb2 = sn & 1;
            for (int i = tid; i < 100; i += 256) {
                int r = i / 10, u = i - r * 10;
                cp16(smem_u32(&s_x[xb2][r * C2_XSTR + 4 * u]), sp + (size_t)(h0 + r) * P2W + w0 + 4 * u);
            }
            CP_COMMIT();
            CP_WAIT1();
        } else {
            CP_WAIT0();
        }
        __syncthreads();

        {
            // d0..d5 at cl 4c4+3 .. 4c4+8 (input cols w0+4c4-1 .. +4)
            const float* xp = &s_x[s & 1][row * C2_XSTR + 4 * c4];
            const float* wcb = &s_w[(s >> 2) & 1][((s & 3) * TOPK + cog * 8) * 24];
            #pragma unroll
            for (int r = 0; r < 3; r++) {
                const float* rp = xp + r * C2_XSTR;
                float  d0 = rp[3];
                float4 A  = *(const float4*)(rp + 4);
                float  d5 = rp[8];
                u64 Q0 = pk2(d0,  A.x);
                u64 Q1 = pk2(A.x, A.y);
                u64 Q2 = pk2(A.y, A.z);
                u64 Q3 = pk2(A.z, A.w);
                u64 Q4 = pk2(A.w, d5);
                #pragma unroll
                for (int j = 0; j < 8; j++) {
                    const u64* wp = (const u64*)(wcb + j * 24 + r * 8);
                    ulonglong2 qq = *(const ulonglong2*)wp;
                    u64 q2 = wp[2];
                    fma2(acc[j][0], Q0, qq.x);
                    fma2(acc[j][0], Q1, qq.y);
                    fma2(acc[j][0], Q2, q2);
                    fma2(acc[j][1], Q2, qq.x);
                    fma2(acc[j][1], Q3, qq.y);
                    fma2(acc[j][1], Q4, q2);
                }
            }
        }
        __syncthreads();
    }

    const int h = h0 + row, w = w0 + 4 * c4;
    #pragma unroll
    for (int j = 0; j < 8; j++) {
        int co = cog * 8 + j;
        float g = s_gv[co];
        int c = s_idx2[co];
        float* base = &out[((size_t)(b * COUT + c) * OH + h) * OW + w];
        float4 id = *(const float4*)base;
        float v0, v1, v2, v3;
        upk2(acc[j][0], v0, v1);
        upk2(acc[j][1], v2, v3);
        float4 o;
        o.x = leaky(leaky(v0 * g) + id.x);
        o.y = leaky(leaky(v1 * g) + id.y);
        o.z = leaky(leaky(v2 * g) + id.z);
        o.w = leaky(leaky(v3 * g) + id.w);
        *(float4*)base = o;
    }
}

// ============================================================================
extern "C" void kernel_launch(void* const* d_in, const int* in_sizes, int n_in,
                              void* d_out, int out_size) {
    const float* x     = (const float*)d_in[0];
    const float* emb   = (const float*)d_in[1];
    const float* w1    = (const float*)d_in[2];
    const float* w2    = (const float*)d_in[3];
    const float* dsw   = (const float*)d_in[4];
    const float* gam   = (const float*)d_in[5];
    const float* bet   = (const float*)d_in[6];
    const float* g1w   = (const float*)d_in[7];
    const float* g1b   = (const float*)d_in[8];
    const float* g2w   = (const float*)d_in[9];
    const float* g2b   = (const float*)d_in[10];
    float* out = (float*)d_out;

    cudaFuncSetAttribute(ds_kernel, cudaFuncAttributeMaxDynamicSharedMemorySize, DS_SMEM);

    gate_kernel<<<dim3(BATCH, 2), 128>>>(emb, g1w, g1b, g2w, g2b, out);
    ds_kernel<<<dim3(144, BATCH), 256, DS_SMEM>>>(x, dsw, gam, bet, out);
    conv1_kernel<<<dim3(72, BATCH), 256>>>(x, w1);
    conv2_kernel<<<dim3(72, BATCH), 256>>>(w2, out);
}

// round 9
// speedup vs baseline: 1.1078x; 1.0038x over previous
#include <cuda_runtime.h>
#include <math.h>

#define BATCH 8
#define CIN   64
#define COUT  128
#define EDIM  128
#define HIN   192
#define WIN   384
#define OH    96
#define OW    192
#define TOPK  32
#define OUT6_SIZE (BATCH*COUT*OH*OW)

// padded conv1->conv2 buffer: out row h at pr=h+1 (98 rows), out col w at pc=w+4 (204 cols)
#define P2H 98
#define P2W 204

typedef unsigned long long u64;

__device__ float d_out2p[BATCH*TOPK*P2H*P2W];
__device__ int   d_idx1[BATCH*TOPK];
__device__ float d_gv1 [BATCH*TOPK];
__device__ int   d_idx2[BATCH*TOPK];
__device__ float d_gv2 [BATCH*TOPK];
__device__ int   d_slot2[BATCH*COUT];

__device__ __forceinline__ float leaky(float v) { return v >= 0.f ? v : 0.2f * v; }

__device__ __forceinline__ u64 pk2(float lo, float hi) {
    u64 r; asm("mov.b64 %0, {%1, %2};" : "=l"(r) : "f"(lo), "f"(hi)); return r;
}
__device__ __forceinline__ void upk2(u64 v, float& lo, float& hi) {
    asm("mov.b64 {%0, %1}, %2;" : "=f"(lo), "=f"(hi) : "l"(v));
}
__device__ __forceinline__ void fma2(u64& d, u64 a, u64 b) {
    asm("fma.rn.f32x2 %0, %1, %2, %0;" : "+l"(d) : "l"(a), "l"(b));
}
__device__ __forceinline__ unsigned smem_u32(const void* p) {
    return (unsigned)__cvta_generic_to_shared(p);
}
__device__ __forceinline__ void cp4(unsigned dst, const void* src, int sz) {
    asm volatile("cp.async.ca.shared.global [%0], [%1], 4, %2;" :: "r"(dst), "l"(src), "r"(sz));
}
__device__ __forceinline__ void cp16(unsigned dst, const void* src) {
    asm volatile("cp.async.ca.shared.global [%0], [%1], 16;" :: "r"(dst), "l"(src));
}
__device__ __forceinline__ void cp16s(unsigned dst, const void* src, int sz) {
    asm volatile("cp.async.ca.shared.global [%0], [%1], 16, %2;" :: "r"(dst), "l"(src), "r"(sz));
}
#define CP_COMMIT() asm volatile("cp.async.commit_group;")
#define CP_WAIT1()  asm volatile("cp.async.wait_group 1;")
#define CP_WAIT0()  asm volatile("cp.async.wait_group 0;")

// ============================================================================
// Gate
// ============================================================================
__global__ void gate_kernel(const float* __restrict__ emb,
                            const float* __restrict__ g1w, const float* __restrict__ g1b,
                            const float* __restrict__ g2w, const float* __restrict__ g2b,
                            float* __restrict__ out) {
    const int b    = blockIdx.x;
    const int gate = blockIdx.y;
    const int c    = threadIdx.x;
    const float* gw = (gate == 0) ? g1w : g2w;
    const float* gb = (gate == 0) ? g1b : g2b;

    __shared__ float s_emb[EDIM];
    __shared__ float s_log[COUT];
    __shared__ float s_exp[COUT];

    s_emb[c] = emb[b * EDIM + c];
    __syncthreads();

    float l = gb[c];
    #pragma unroll 8
    for (int e = 0; e < EDIM; e++) l += s_emb[e] * gw[e * COUT + c];
    s_log[c] = l;
    __syncthreads();

    int rank = 0;
    float m = -1e30f;
    for (int j = 0; j < COUT; j++) {
        float lj = s_log[j];
        if (lj > l || (lj == l && j < c)) rank++;
        if (lj > m) m = lj;
    }
    bool sel = (rank < TOPK);
    float ev = sel ? expf(l - m) : 0.0f;
    s_exp[c] = ev;
    __syncthreads();

    float s = 0.f;
    for (int j = 0; j < COUT; j++) s += s_exp[j];
    float gv = ev / s;

    out[OUT6_SIZE + gate * (BATCH * COUT) + b * COUT + c] = gv;

    if (gate == 0) {
        if (sel) { d_idx1[b * TOPK + rank] = c; d_gv1[b * TOPK + rank] = gv; }
    } else {
        d_slot2[b * COUT + c] = sel ? rank : -1;
        if (sel) { d_idx2[b * TOPK + rank] = c; d_gv2[b * TOPK + rank] = gv; }
    }
}

// ============================================================================
// ds: all 128 co per block, x staged once. Tile 8x16 px. (unchanged from R7)
// ============================================================================
#define DS_SMEM ((8192 + 8192 + 384) * 4)
__global__ void __launch_bounds__(256, 2) ds_kernel(const float* __restrict__ x,
                                                    const float* __restrict__ dsw,
                                                    const float* __restrict__ gamma,
                                                    const float* __restrict__ beta,
                                                    float* __restrict__ out) {
    extern __shared__ __align__(16) float dsm[];
    float* s_xc    = dsm;
    float* s_wt    = dsm + 8192;
    float* s_scale = dsm + 16384;
    float* s_betav = s_scale + 128;
    int*   s_slot  = (int*)(s_betav + 128);

    const int b  = blockIdx.y;
    const int h0 = (blockIdx.x / 12) * 8;
    const int w0 = (blockIdx.x % 12) * 16;
    const int tid = threadIdx.x;
    const int po  = tid >> 4;
    const int cg  = tid & 15;

    const float* xb = x + (size_t)b * CIN * HIN * WIN;
    #pragma unroll 8
    for (int k = 0; k < 32; k++) {
        int i = tid + k * 256;
        int ci = i >> 7, p = i & 127, r = (p >> 4), j = p & 15;
        cp4(smem_u32(&s_xc[i]), xb + (size_t)ci * HIN * WIN + (2 * (h0 + r)) * WIN + 2 * (w0 + j), 4);
    }
    #pragma unroll 8
    for (int k = 0; k < 32; k++) {
        int i = tid + k * 256;
        int co = i >> 6, ci = i & 63;
        cp4(smem_u32(&s_wt[ci * 128 + co]), dsw + i, 4);
    }
    if (tid < 128) {
        s_scale[tid] = gamma[tid] * rsqrtf(1.0f + 1e-5f);
        s_betav[tid] = beta[tid];
        s_slot[tid]  = d_slot2[b * COUT + tid];
    }
    CP_COMMIT(); CP_WAIT0();
    __syncthreads();

    u64 acc[8][4];
    #pragma unroll
    for (int c = 0; c < 8; c++)
        #pragma unroll
        for (int m = 0; m < 4; m++) acc[c][m] = 0ull;

    #pragma unroll 4
    for (int ci = 0; ci < 64; ci++) {
        const ulonglong2* xq = (const ulonglong2*)&s_xc[ci * 128 + 8 * po];
        ulonglong2 X0 = xq[0], X1 = xq[1];
        const float4* wq = (const float4*)&s_wt[ci * 128 + 8 * cg];
        float4 wa = wq[0], wb2 = wq[1];
        u64 W[8];
        W[0] = pk2(wa.x, wa.x);   W[1] = pk2(wa.y, wa.y);
        W[2] = pk2(wa.z, wa.z);   W[3] = pk2(wa.w, wa.w);
        W[4] = pk2(wb2.x, wb2.x); W[5] = pk2(wb2.y, wb2.y);
        W[6] = pk2(wb2.z, wb2.z); W[7] = pk2(wb2.w, wb2.w);
        #pragma unroll
        for (int c = 0; c < 8; c++) {
            fma2(acc[c][0], X0.x, W[c]);
            fma2(acc[c][1], X0.y, W[c]);
            fma2(acc[c][2], X1.x, W[c]);
            fma2(acc[c][3], X1.y, W[c]);
        }
    }

    const int hr  = h0 + (po >> 1);
    const int wc0 = w0 + (po & 1) * 8;
    #pragma unroll
    for (int c = 0; c < 8; c++) {
        int co = 8 * cg + c;
        float v[8];
        #pragma unroll
        for (int m = 0; m < 4; m++) upk2(acc[c][m], v[2 * m], v[2 * m + 1]);
        float sc = s_scale[co], be = s_betav[co];
        #pragma unroll
        for (int k = 0; k < 8; k++) v[k] = v[k] * sc + be;
        if (s_slot[co] < 0) {
            #pragma unroll
            for (int k = 0; k < 8; k++) v[k] = leaky(v[k]);
        }
        float* base = &out[((size_t)(b * COUT + co) * OH + hr) * OW + wc0];
        *(float4*)base       = make_float4(v[0], v[1], v[2], v[3]);
        *(float4*)(base + 4) = make_float4(v[4], v[5], v[6], v[7]);
    }
}

// ============================================================================
// conv1: 3x3 s2 p1, 32 gated channels. Thread: 8 co x 4 px (low regs, 3 CTA).
// Tile 8x32 out px. grid (72, BATCH). s_x cols from 2w0-4, stride 68.
// ============================================================================
#define C1_XSTR 68
__global__ void __launch_bounds__(256, 3) conv1_kernel(const float* __restrict__ x,
                                                       const float* __restrict__ w1) {
    const int b = blockIdx.y, tile = blockIdx.x;
    const int h0 = (tile / 6) * 8, w0 = (tile % 6) * 32;
    const int tid = threadIdx.x;
    const int cog = tid >> 6;
    const int t   = tid & 63;
    const int row = t >> 3;
    const int c4  = t & 7;

    __shared__ int   s_idx[TOPK];
    __shared__ float s_gv[TOPK];
    __shared__ __align__(16) float s_w[2][4 * TOPK * 24];   // 24.6 KB
    __shared__ __align__(16) float s_x[2][17 * C1_XSTR];    // 9.2 KB

    if (tid < TOPK) { s_idx[tid] = d_idx1[b * TOPK + tid]; s_gv[tid] = d_gv1[b * TOPK + tid]; }
    __syncthreads();

    u64 acc[8][2];
    #pragma unroll
    for (int i = 0; i < 8; i++) { acc[i][0] = 0ull; acc[i][1] = 0ull; }

    // prologue
    {
        for (int i = tid; i < 4 * TOPK * 9; i += 256) {
            int ci_l = i / (TOPK * 9);
            int r = i - ci_l * (TOPK * 9);
            int co = r / 9, k = r - co * 9;
            const float* src = w1 + (s_idx[co] * CIN + ci_l) * 9 + k;
            unsigned dst = smem_u32(&s_w[0][(ci_l * TOPK + co) * 24 + (k / 3) * 8 + (k % 3) * 2]);
            cp4(dst, src, 4); cp4(dst + 4, src, 4);
        }
        const float* sp = x + (size_t)(b * CIN + 0) * HIN * WIN;
        for (int i = tid; i < 289; i += 256) {
            int r = i / 17, u = i - r * 17;
            int gr = 2 * h0 - 1 + r, gc = 2 * w0 - 4 + 4 * u;
            int ok = (gr >= 0 && gc >= 0) ? 16 : 0;
            cp16s(smem_u32(&s_x[0][r * C1_XSTR + 4 * u]), sp + (size_t)gr * WIN + gc, ok);
        }
        CP_COMMIT();
    }

    for (int s = 0; s < CIN; s++) {
        if (s + 1 < CIN) {
            const int sn = s + 1;
            if ((sn & 3) == 0) {
                const int chunk = sn >> 2, wb = chunk & 1;
                for (int i = tid; i < 4 * TOPK * 9; i += 256) {
                    int ci_l = i / (TOPK * 9);
                    int r = i - ci_l * (TOPK * 9);
                    int co = r / 9, k = r - co * 9;
                    const float* src = w1 + (s_idx[co] * CIN + chunk * 4 + ci_l) * 9 + k;
                    unsigned dst = smem_u32(&s_w[wb][(ci_l * TOPK + co) * 24 + (k / 3) * 8 + (k % 3) * 2]);
                    cp4(dst, src, 4); cp4(dst + 4, src, 4);
                }
            }
            const float* sp = x + (size_t)(b * CIN + sn) * HIN * WIN;
            const int xb2 = sn & 1;
            for (int i = tid; i < 289; i += 256) {
                int r = i / 17, u = i - r * 17;
                int gr = 2 * h0 - 1 + r, gc = 2 * w0 - 4 + 4 * u;
                int ok = (gr >= 0 && gc >= 0) ? 16 : 0;
                cp16s(smem_u32(&s_x[xb2][r * C1_XSTR + 4 * u]), sp + (size_t)gr * WIN + gc, ok);
            }
            CP_COMMIT();
            CP_WAIT1();
        } else {
            CP_WAIT0();
        }
        __syncthreads();

        {
            // p0..p8 at cl 8c4+3 .. 8c4+11 (input cols 2(w0+4c4)-1 .. +7)
            const float* xp = &s_x[s & 1][(2 * row) * C1_XSTR + 8 * c4];
            const float* wcb = &s_w[(s >> 2) & 1][((s & 3) * TOPK + cog * 8) * 24];
            #pragma unroll
            for (int r = 0; r < 3; r++) {
                const float* rp = xp + r * C1_XSTR;
                float  p0 = rp[3];
                float4 A0 = *(const float4*)(rp + 4);
                float4 A1 = *(const float4*)(rp + 8);
                u64 S00 = pk2(p0,   A0.y);
                u64 S01 = pk2(A0.x, A0.z);
                u64 S02 = pk2(A0.y, A0.w);
                u64 S10 = pk2(A0.w, A1.y);
                u64 S11 = pk2(A1.x, A1.z);
                u64 S12 = pk2(A1.y, A1.w);
                #pragma unroll
                for (int j = 0; j < 8; j++) {
                    const u64* wp = (const u64*)(wcb + j * 24 + r * 8);
                    ulonglong2 qq = *(const ulonglong2*)wp;
                    u64 q2 = wp[2];
                    fma2(acc[j][0], S00, qq.x);
                    fma2(acc[j][0], S01, qq.y);
                    fma2(acc[j][0], S02, q2);
                    fma2(acc[j][1], S10, qq.x);
                    fma2(acc[j][1], S11, qq.y);
                    fma2(acc[j][1], S12, q2);
                }
            }
        }
        __syncthreads();
    }

    const int h = h0 + row, w = w0 + 4 * c4;
    #pragma unroll
    for (int j = 0; j < 8; j++) {
        int co = cog * 8 + j;
        float g = s_gv[co];
        float v0, v1, v2, v3;
        upk2(acc[j][0], v0, v1);
        upk2(acc[j][1], v2, v3);
        float4 o;
        o.x = leaky(v0 * g); o.y = leaky(v1 * g);
        o.z = leaky(v2 * g); o.w = leaky(v3 * g);
        *(float4*)&d_out2p[((size_t)(b * TOPK + co) * P2H + h + 1) * P2W + (w + 4)] = o;
    }
}

// ============================================================================
// conv2: 3x3 s1 p1, 32 in -> 32 gated out, fused leaky(leaky(conv*g2)+ident).
// Thread: 8 co x 4 px. Tile 8x32. grid (72, BATCH). s_x stride 40, from pc w0.
// ============================================================================
#define C2_XSTR 40
__global__ void __launch_bounds__(256, 3) conv2_kernel(const float* __restrict__ w2,
                                                       float* __restrict__ out) {
    const int b = blockIdx.y, tile = blockIdx.x;
    const int h0 = (tile / 6) * 8, w0 = (tile % 6) * 32;
    const int tid = threadIdx.x;
    const int cog = tid >> 6;
    const int t   = tid & 63;
    const int row = t >> 3;
    const int c4  = t & 7;

    __shared__ int   s_idx1[TOPK];
    __shared__ int   s_idx2[TOPK];
    __shared__ float s_gv[TOPK];
    __shared__ __align__(16) float s_w[2][4 * TOPK * 24];   // 24.6 KB
    __shared__ __align__(16) float s_x[2][10 * C2_XSTR];    // 3.2 KB

    if (tid < TOPK) {
        s_idx1[tid] = d_idx1[b * TOPK + tid];
        s_idx2[tid] = d_idx2[b * TOPK + tid];
        s_gv[tid]   = d_gv2[b * TOPK + tid];
    }
    __syncthreads();

    u64 acc[8][2];
    #pragma unroll
    for (int i = 0; i < 8; i++) { acc[i][0] = 0ull; acc[i][1] = 0ull; }

    // prologue
    {
        for (int i = tid; i < 4 * TOPK * 9; i += 256) {
            int ci_l = i / (TOPK * 9);
            int r = i - ci_l * (TOPK * 9);
            int co = r / 9, k = r - co * 9;
            const float* src = w2 + (s_idx2[co] * COUT + s_idx1[ci_l]) * 9 + k;
            unsigned dst = smem_u32(&s_w[0][(ci_l * TOPK + co) * 24 + (k / 3) * 8 + (k % 3) * 2]);
            cp4(dst, src, 4); cp4(dst + 4, src, 4);
        }
        const float* sp = d_out2p + (size_t)(b * TOPK + 0) * P2H * P2W;
        for (int i = tid; i < 100; i += 256) {
            int r = i / 10, u = i - r * 10;
            cp16(smem_u32(&s_x[0][r * C2_XSTR + 4 * u]), sp + (size_t)(h0 + r) * P2W + w0 + 4 * u);
        }
        CP_COMMIT();
    }

    for (int s = 0; s < TOPK; s++) {
        if (s + 1 < TOPK) {
            const int sn = s + 1;
            if ((sn & 3) == 0) {
                const int chunk = sn >> 2, wb = chunk & 1;
                for (int i = tid; i < 4 * TOPK * 9; i += 256) {
                    int ci_l = i / (TOPK * 9);
                    int r = i - ci_l * (TOPK * 9);
                    int co = r / 9, k = r - co * 9;
                    const float* src = w2 + (s_idx2[co] * COUT + s_idx1[chunk * 4 + ci_l]) * 9 + k;
                    unsigned dst = smem_u32(&s_w[wb][(ci_l * TOPK + co) * 24 + (k / 3) * 8 + (k % 3) * 2]);
                    cp4(dst, src, 4); cp4(dst + 4, src, 4);
                }
            }
            const float* sp = d_out2p + (size_t)(b * TOPK + sn) * P2H * P2W;
            const int xb2 = sn & 1;
            for (int i = tid; i < 100; i += 256) {
                int r = i / 10, u = i - r * 10;
                cp16(smem_u32(&s_x[xb2][r * C2_XSTR + 4 * u]), sp + (size_t)(h0 + r) * P2W + w0 + 4 * u);
            }
            CP_COMMIT();
            CP_WAIT1();
        } else {
            CP_WAIT0();
        }
        __syncthreads();

        {
            // d0..d5 at cl 4c4+3 .. 4c4+8 (input cols w0+4c4-1 .. +4)
            const float* xp = &s_x[s & 1][row * C2_XSTR + 4 * c4];
            const float* wcb = &s_w[(s >> 2) & 1][((s & 3) * TOPK + cog * 8) * 24];
            #pragma unroll
            for (int r = 0; r < 3; r++) {
                const float* rp = xp + r * C2_XSTR;
                float  d0 = rp[3];
                float4 A  = *(const float4*)(rp + 4);
                float  d5 = rp[8];
                u64 Q0 = pk2(d0,  A.x);
                u64 Q1 = pk2(A.x, A.y);
                u64 Q2 = pk2(A.y, A.z);
                u64 Q3 = pk2(A.z, A.w);
                u64 Q4 = pk2(A.w, d5);
                #pragma unroll
                for (int j = 0; j < 8; j++) {
                    const u64* wp = (const u64*)(wcb + j * 24 + r * 8);
                    ulonglong2 qq = *(const ulonglong2*)wp;
                    u64 q2 = wp[2];
                    fma2(acc[j][0], Q0, qq.x);
                    fma2(acc[j][0], Q1, qq.y);
                    fma2(acc[j][0], Q2, q2);
                    fma2(acc[j][1], Q2, qq.x);
                    fma2(acc[j][1], Q3, qq.y);
                    fma2(acc[j][1], Q4, q2);
                }
            }
        }
        __syncthreads();
    }

    const int h = h0 + row, w = w0 + 4 * c4;
    #pragma unroll
    for (int j = 0; j < 8; j++) {
        int co = cog * 8 + j;
        float g = s_gv[co];
        int c = s_idx2[co];
        float* base = &out[((size_t)(b * COUT + c) * OH + h) * OW + w];
        float4 id = *(const float4*)base;
        float v0, v1, v2, v3;
        upk2(acc[j][0], v0, v1);
        upk2(acc[j][1], v2, v3);
        float4 o;
        o.x = leaky(leaky(v0 * g) + id.x);
        o.y = leaky(leaky(v1 * g) + id.y);
        o.z = leaky(leaky(v2 * g) + id.z);
        o.w = leaky(leaky(v3 * g) + id.w);
        *(float4*)base = o;
    }
}

// ============================================================================
extern "C" void kernel_launch(void* const* d_in, const int* in_sizes, int n_in,
                              void* d_out, int out_size) {
    const float* x     = (const float*)d_in[0];
    const float* emb   = (const float*)d_in[1];
    const float* w1    = (const float*)d_in[2];
    const float* w2    = (const float*)d_in[3];
    const float* dsw   = (const float*)d_in[4];
    const float* gam   = (const float*)d_in[5];
    const float* bet   = (const float*)d_in[6];
    const float* g1w   = (const float*)d_in[7];
    const float* g1b   = (const float*)d_in[8];
    const float* g2w   = (const float*)d_in[9];
    const float* g2b   = (const float*)d_in[10];
    float* out = (float*)d_out;

    cudaFuncSetAttribute(ds_kernel, cudaFuncAttributeMaxDynamicSharedMemorySize, DS_SMEM);

    gate_kernel<<<dim3(BATCH, 2), 128>>>(emb, g1w, g1b, g2w, g2b, out);
    ds_kernel<<<dim3(144, BATCH), 256, DS_SMEM>>>(x, dsw, gam, bet, out);
    conv1_kernel<<<dim3(72, BATCH), 256>>>(x, w1);
    conv2_kernel<<<dim3(72, BATCH), 256>>>(w2, out);
}